// round 5
// baseline (speedup 1.0000x reference)
#include <cuda_runtime.h>
#include <cuda_bf16.h>
#include <cstdint>

#define NB   32
#define NL   1023
#define NS   1024
#define NH   256
#define NC2  512
#define NE   256
#define NM1  32768
#define NM2  32736

// ---------------- scratch ----------------------------------------------------
__device__ __nv_bfloat16 g_Ghi[NM1 * NE],  g_Glo[NM1 * NE];
__device__ float         g_Y  [NM2 * NC2];
__device__ __nv_bfloat16 g_Dhi[NM2 * NH],  g_Dlo[NM2 * NH];
__device__ float         g_SC [(long)NM2 * NS];
__device__ __nv_bfloat16 g_AThi[(long)NM2 * NS], g_ATlo[(long)NM2 * NS];
__device__ __nv_bfloat16 g_CWh[NC2 * 1536], g_CWl[NC2 * 1536];  // conv_w split flat
__device__ __nv_bfloat16 g_AWT[NE * 3 * NC2];                   // affine_w^T [h|l|h]
__device__ __nv_bfloat16 g_FWB[NC2 * 3 * 768];                  // fused weight [h|l|h]
__device__ __nv_bfloat16 g_MWb[NC2 * 3 * NH];
__device__ __nv_bfloat16 g_EAb[(long)NB * NS * 3 * NH];
__device__ __nv_bfloat16 g_SST[(long)NB * NC2 * 3 * NS];
__device__ float         g_BC [3 * NC2];
__device__ float         g_BR [3 * NC2];

// ---------------- helpers ----------------------------------------------------
__device__ __forceinline__ uint32_t smem_u32(const void* p) {
    uint32_t a;
    asm("{ .reg .u64 t; cvta.to.shared.u64 t, %1; cvt.u32.u64 %0, t; }" : "=r"(a) : "l"(p));
    return a;
}
__device__ __forceinline__ void cpasync16(uint32_t s, const void* g, bool pred) {
    int sz = pred ? 16 : 0;
    asm volatile("cp.async.cg.shared.global [%0], [%1], 16, %2;\n" :: "r"(s), "l"(g), "r"(sz));
}
__device__ __forceinline__ void cp_commit() { asm volatile("cp.async.commit_group;\n" ::: "memory"); }

__device__ __forceinline__ void ldm4(uint32_t* r, uint32_t a) {
    asm volatile("ldmatrix.sync.aligned.m8n8.x4.shared.b16 {%0,%1,%2,%3}, [%4];"
                 : "=r"(r[0]), "=r"(r[1]), "=r"(r[2]), "=r"(r[3]) : "r"(a));
}
__device__ __forceinline__ void mma16816(float* c, const uint32_t* a, const uint32_t* b) {
    asm volatile(
        "mma.sync.aligned.m16n8k16.row.col.f32.bf16.bf16.f32 "
        "{%0,%1,%2,%3}, {%4,%5,%6,%7}, {%8,%9}, {%0,%1,%2,%3};"
        : "+f"(c[0]), "+f"(c[1]), "+f"(c[2]), "+f"(c[3])
        : "r"(a[0]), "r"(a[1]), "r"(a[2]), "r"(a[3]), "r"(b[0]), "r"(b[1]));
}
__device__ __forceinline__ void split2(float v, __nv_bfloat16& h, __nv_bfloat16& l) {
    h = __float2bfloat16(v);
    l = __float2bfloat16(v - __bfloat162float(h));
}

// ---------------- conversion kernels ----------------------------------------
__global__ void split_bhl(const float* __restrict__ src, __nv_bfloat16* __restrict__ dst,
                          int K, long total) {
    long gid = (long)blockIdx.x * blockDim.x + threadIdx.x;
    if (gid >= total) return;
    long n = gid / K;
    int  k = (int)(gid - n * K);
    float v = src[gid];
    __nv_bfloat16 h, l; split2(v, h, l);
    long b0 = n * 3 * (long)K;
    dst[b0 + k] = h;
    dst[b0 + K + k] = l;
    dst[b0 + 2 * K + k] = h;
}

__global__ void split_flat(const float* __restrict__ src, long total) {
    long gid = (long)blockIdx.x * blockDim.x + threadIdx.x;
    if (gid >= total) return;
    __nv_bfloat16 h, l; split2(src[gid], h, l);
    g_CWh[gid] = h; g_CWl[gid] = l;
}

__global__ void awt_kernel(const float* __restrict__ aw) {
    __shared__ float tile[32][33];
    int i0 = blockIdx.x * 32, e0 = blockIdx.y * 32;
    int tx = threadIdx.x, ty = threadIdx.y;
    tile[ty][tx] = aw[(i0 + ty) * NE + e0 + tx];
    __syncthreads();
    float v = tile[tx][ty];
    __nv_bfloat16 h, l; split2(v, h, l);
    long base = (long)(e0 + ty) * 1536 + i0 + tx;
    g_AWT[base] = h; g_AWT[base + 512] = l; g_AWT[base + 1024] = h;
}

__global__ void bconst_kernel(const float* __restrict__ cw, const float* __restrict__ ab) {
    int wid = (blockIdx.x * blockDim.x + threadIdx.x) >> 5;
    int lane = threadIdx.x & 31;
    if (wid >= 1536) return;
    int tap = wid / 512, o = wid % 512;
    const float* row = cw + (long)o * 1536 + tap * 512;
    float s = 0.f;
    for (int i = lane; i < 512; i += 32) s += row[i] * ab[i];
    #pragma unroll
    for (int off = 16; off > 0; off >>= 1) s += __shfl_xor_sync(~0u, s, off);
    if (lane == 0) g_BC[tap * 512 + o] = s;
}

__global__ void biasrows_kernel(const float* __restrict__ conv_b) {
    int o = blockIdx.x * blockDim.x + threadIdx.x;
    if (o >= 512) return;
    float b = conv_b[o];
    float c0 = g_BC[o], c1 = g_BC[512 + o], c2 = g_BC[1024 + o];
    g_BR[o]        = b + c2;
    g_BR[512 + o]  = b + c1 + c2;
    g_BR[1024 + o] = b + c0 + c1 + c2;
}

__global__ void gather_split(const int* __restrict__ target, const float* __restrict__ emb) {
    long gid = (long)blockIdx.x * blockDim.x + threadIdx.x;
    if (gid >= (long)NM1 * NE) return;
    int m = (int)(gid >> 8);
    int k = (int)(gid & 255);
    int b = m >> 10, t = m & 1023;
    int idx = target[t * NB + b];
    float v = emb[(long)idx * NE + k];
    __nv_bfloat16 h, l; split2(v, h, l);
    g_Ghi[gid] = h; g_Glo[gid] = l;
}

__global__ void sst_kernel(const float* __restrict__ src) {
    __shared__ float tile[32][33];
    int b = blockIdx.z;
    int s0 = blockIdx.x * 32, d0 = blockIdx.y * 32;
    int tx = threadIdx.x, ty = threadIdx.y;
    tile[ty][tx] = src[((long)b * NS + s0 + ty) * NC2 + d0 + tx];
    __syncthreads();
    int d = d0 + ty, s = s0 + tx;
    float v = tile[tx][ty];
    __nv_bfloat16 h, l; split2(v, h, l);
    long base = ((long)b * NC2 + d) * (3 * NS) + s;
    g_SST[base] = h; g_SST[base + NS] = l; g_SST[base + 2 * NS] = h;
}

__global__ void glu_kernel() {
    int m = blockIdx.x;
    int h = threadIdx.x;
    float a = g_Y[(long)m * NC2 + h];
    float g = g_Y[(long)m * NC2 + NH + h];
    a = fmaxf(a, 0.f); g = fmaxf(g, 0.f);
    __shared__ float red[8];
    float v = g;
    #pragma unroll
    for (int o = 16; o > 0; o >>= 1) v = fmaxf(v, __shfl_xor_sync(~0u, v, o));
    if ((h & 31) == 0) red[h >> 5] = v;
    __syncthreads();
    float mx = red[0];
    #pragma unroll
    for (int i = 1; i < 8; i++) mx = fmaxf(mx, red[i]);
    float e = expf(g - mx);
    __syncthreads();
    v = e;
    #pragma unroll
    for (int o = 16; o > 0; o >>= 1) v += __shfl_xor_sync(~0u, v, o);
    if ((h & 31) == 0) red[h >> 5] = v;
    __syncthreads();
    float sum = 0.f;
    #pragma unroll
    for (int i = 0; i < 8; i++) sum += red[i];
    float dec = a * e / sum;
    __nv_bfloat16 hi, lo; split2(dec, hi, lo);
    g_Dhi[(long)m * NH + h] = hi;
    g_Dlo[(long)m * NH + h] = lo;
}

__global__ void softmax_rows_kernel() {
    int m = blockIdx.x;
    int h = threadIdx.x;
    const float* row = g_SC + (long)m * NS;
    float x0 = row[h], x1 = row[h + 256], x2 = row[h + 512], x3 = row[h + 768];
    __shared__ float red[8];
    float v = fmaxf(fmaxf(x0, x1), fmaxf(x2, x3));
    #pragma unroll
    for (int o = 16; o > 0; o >>= 1) v = fmaxf(v, __shfl_xor_sync(~0u, v, o));
    if ((h & 31) == 0) red[h >> 5] = v;
    __syncthreads();
    float mx = red[0];
    #pragma unroll
    for (int i = 1; i < 8; i++) mx = fmaxf(mx, red[i]);
    float e0 = expf(x0 - mx), e1 = expf(x1 - mx), e2 = expf(x2 - mx), e3 = expf(x3 - mx);
    __syncthreads();
    v = e0 + e1 + e2 + e3;
    #pragma unroll
    for (int o = 16; o > 0; o >>= 1) v += __shfl_xor_sync(~0u, v, o);
    if ((h & 31) == 0) red[h >> 5] = v;
    __syncthreads();
    float sum = 0.f;
    #pragma unroll
    for (int i = 0; i < 8; i++) sum += red[i];
    float inv = 1.f / sum;
    long base = (long)m * NS;
    #pragma unroll
    for (int q = 0; q < 4; q++) {
        float e = (q == 0 ? e0 : q == 1 ? e1 : q == 2 ? e2 : e3) * inv;
        __nv_bfloat16 hi, lo; split2(e, hi, lo);
        g_AThi[base + h + q * 256] = hi;
        g_ATlo[base + h + q * 256] = lo;
    }
}

// ---------------- mma.sync bf16 GEMM, 128x256 tile, 64x64 warp tile ----------
// C[M, N] = A'[M, 3K] * B'[N, 3K]^T ; A' logical [Ahi | Ahi | Alo], B' = [hi|lo|hi].
// BK=32, 4-stage cp.async, 256 thr (8 warps, 2x4 -> 64x64 warp tile).
// AMODE 0: rows (z*Mb + l) * lda + k.  AMODE 2 (fused conv on G): k -> (tap, e),
//          t = l-2+tap, read (z*1024+t)*256 + e; zero-fill t<0.
// EPI: 0 f32+bias1D, 1 f32, 2 f32 accumulate,
//      3 FW split write ([h|l|h] at +0/+768/+1536, ld 2304, no bias),
//      5 f32 + bias2D rows BR[min(l,2)].
#define STAGE_BYTES (24 * 1024)
#define GEMM_SMEM (4 * STAGE_BYTES)

template <int AMODE, int EPI>
__global__ __launch_bounds__(256, 1)
void gemm_mma(const __nv_bfloat16* __restrict__ Ahi, const __nv_bfloat16* __restrict__ Alo,
              int KB, int lda, const __nv_bfloat16* __restrict__ Bm, long bBatch,
              const float* __restrict__ bias,
              float* __restrict__ C, int cLd,
              __nv_bfloat16* __restrict__ Ohi,
              int Mb) {
    extern __shared__ char smem[];
    const uint32_t sb = smem_u32(smem);
    const int tid = threadIdx.x;
    const int z  = blockIdx.z;
    const int l0 = blockIdx.y * 128;
    const int n0 = blockIdx.x * 256;
    const int Kp = 3 * KB;
    const int NK = Kp / 32;
    const __nv_bfloat16* Bb = Bm + (long)z * bBatch;

    auto load_tile = [&](int kt, int st) {
        const int k0 = kt * 32;
        const int seg = k0 / KB;
        const int rem0 = k0 - seg * KB;
        const __nv_bfloat16* Ab = (seg < 2) ? Ahi : Alo;
        const uint32_t sA = sb + st * STAGE_BYTES;
        const uint32_t sB = sA + 8192;
        #pragma unroll
        for (int i = 0; i < 2; i++) {
            int c = tid + i * 256;          // 0..511
            int m = c >> 2, kc = c & 3;
            int l = l0 + m;
            long g; bool ok;
            if (AMODE == 0) {
                ok = (l < Mb);
                g = ((long)z * Mb + l) * (long)lda + rem0 + kc * 8;
            } else {                         // fused conv on G
                int tap = rem0 >> 8;
                int e = (rem0 & 255) + kc * 8;
                int t = l - 2 + tap;
                ok = (l < Mb) && (t >= 0);
                g = ((long)z * 1024 + t) * 256 + e;
            }
            cpasync16(sA + m * 64 + ((uint32_t)(kc ^ (m & 3)) << 4), Ab + (ok ? g : 0), ok);
        }
        #pragma unroll
        for (int i = 0; i < 4; i++) {
            int c = tid + i * 256;          // 0..1023
            int n = c >> 2, kc = c & 3;
            cpasync16(sB + n * 64 + ((uint32_t)(kc ^ (n & 3)) << 4),
                      Bb + (long)(n0 + n) * Kp + k0 + kc * 8, true);
        }
        cp_commit();
    };

    float acc[4][8][4];
    #pragma unroll
    for (int i = 0; i < 4; i++)
        #pragma unroll
        for (int j = 0; j < 8; j++)
            #pragma unroll
            for (int q = 0; q < 4; q++) acc[i][j][q] = 0.f;

    const int w = tid >> 5, lid = tid & 31;
    const int wm = w >> 2, wn = w & 3;          // warp grid 2 x 4
    const int rl = wm * 64 + (lid & 15);        // A ldmatrix row
    const int aC = lid >> 4;                    // A k-chunk bit
    const int nl = wn * 64 + ((lid >> 4) << 3) + (lid & 7);  // B ldmatrix row
    const int bC = (lid >> 3) & 1;              // B k-chunk bit

    load_tile(0, 0); load_tile(1, 1); load_tile(2, 2);

    for (int kt = 0; kt < NK; kt++) {
        const int st = kt & 3;
        asm volatile("cp.async.wait_group 2;\n" ::: "memory");
        __syncthreads();
        if (kt + 3 < NK) load_tile(kt + 3, (kt + 3) & 3);
        else cp_commit();

        const uint32_t sA = sb + st * STAGE_BYTES;
        const uint32_t sB = sA + 8192;
        #pragma unroll
        for (int ks = 0; ks < 2; ks++) {
            uint32_t a[4][4];
            #pragma unroll
            for (int i = 0; i < 4; i++) {
                int r = rl + i * 16;
                ldm4(a[i], sA + r * 64 + ((uint32_t)((ks * 2 + aC) ^ (r & 3)) << 4));
            }
            uint32_t b[8][2];
            #pragma unroll
            for (int jj = 0; jj < 4; jj++) {
                int n = nl + jj * 16;
                uint32_t t[4];
                ldm4(t, sB + n * 64 + ((uint32_t)((ks * 2 + bC) ^ (n & 3)) << 4));
                b[jj * 2][0] = t[0]; b[jj * 2][1] = t[1];
                b[jj * 2 + 1][0] = t[2]; b[jj * 2 + 1][1] = t[3];
            }
            #pragma unroll
            for (int i = 0; i < 4; i++)
                #pragma unroll
                for (int j = 0; j < 8; j++)
                    mma16816(acc[i][j], a[i], b[j]);
        }
    }

    // ---------------- epilogue ----------------
    const int g  = lid >> 2, t4 = lid & 3;
    #pragma unroll
    for (int i = 0; i < 4; i++) {
        #pragma unroll
        for (int h = 0; h < 2; h++) {
            int row = l0 + wm * 64 + i * 16 + g + h * 8;
            if (row >= Mb) continue;
            long grow = (long)z * Mb + row;
            #pragma unroll
            for (int j = 0; j < 8; j++) {
                int col = n0 + wn * 64 + j * 8 + 2 * t4;
                float v0 = acc[i][j][h * 2 + 0];
                float v1 = acc[i][j][h * 2 + 1];
                if (EPI == 0) { v0 += bias[col]; v1 += bias[col + 1]; }
                if (EPI == 5) {
                    int jb = (row < 2) ? row : 2;
                    v0 += bias[jb * 512 + col]; v1 += bias[jb * 512 + col + 1];
                }
                if (EPI == 3) {
                    __nv_bfloat16 h0, lb0, h1, lb1;
                    split2(v0, h0, lb0); split2(v1, h1, lb1);
                    __nv_bfloat162 hh; hh.x = h0; hh.y = h1;
                    __nv_bfloat162 ll; ll.x = lb0; ll.y = lb1;
                    long base = grow * 2304 + col;
                    *(__nv_bfloat162*)(Ohi + base)        = hh;
                    *(__nv_bfloat162*)(Ohi + base + 768)  = ll;
                    *(__nv_bfloat162*)(Ohi + base + 1536) = hh;
                } else {
                    float* cp = C + grow * (long)cLd + col;
                    if (EPI == 2) { v0 += cp[0]; v1 += cp[1]; }
                    float2 r; r.x = v0; r.y = v1;
                    *(float2*)cp = r;
                }
            }
        }
    }
}

// ---------------- launcher ---------------------------------------------------
extern "C" void kernel_launch(void* const* d_in, const int* in_sizes, int n_in,
                              void* d_out, int out_size) {
    const int*   target   = (const int*)d_in[1];
    const float* enc_attn = (const float*)d_in[2];
    const float* src_seq  = (const float*)d_in[3];
    const float* emb      = (const float*)d_in[4];
    const float* affine_w = (const float*)d_in[5];
    const float* affine_b = (const float*)d_in[6];
    const float* conv_w   = (const float*)d_in[7];
    const float* conv_b   = (const float*)d_in[8];
    const float* map_w    = (const float*)d_in[9];
    const float* map_b    = (const float*)d_in[10];
    float* out = (float*)d_out;

    __nv_bfloat16 *Ghi, *Glo, *Dhi, *Dlo, *AThi, *ATlo, *CWh, *CWl, *AWT, *FWB, *MWb, *EAb, *SST;
    float *Y, *SC, *BR;
    cudaGetSymbolAddress((void**)&Ghi, g_Ghi);   cudaGetSymbolAddress((void**)&Glo, g_Glo);
    cudaGetSymbolAddress((void**)&Y,   g_Y);
    cudaGetSymbolAddress((void**)&Dhi, g_Dhi);   cudaGetSymbolAddress((void**)&Dlo, g_Dlo);
    cudaGetSymbolAddress((void**)&SC,  g_SC);
    cudaGetSymbolAddress((void**)&AThi, g_AThi); cudaGetSymbolAddress((void**)&ATlo, g_ATlo);
    cudaGetSymbolAddress((void**)&CWh, g_CWh);   cudaGetSymbolAddress((void**)&CWl, g_CWl);
    cudaGetSymbolAddress((void**)&AWT, g_AWT);   cudaGetSymbolAddress((void**)&FWB, g_FWB);
    cudaGetSymbolAddress((void**)&MWb, g_MWb);   cudaGetSymbolAddress((void**)&EAb, g_EAb);
    cudaGetSymbolAddress((void**)&SST, g_SST);   cudaGetSymbolAddress((void**)&BR,  g_BR);

    cudaFuncSetAttribute(gemm_mma<0, 3>, cudaFuncAttributeMaxDynamicSharedMemorySize, GEMM_SMEM);
    cudaFuncSetAttribute(gemm_mma<2, 5>, cudaFuncAttributeMaxDynamicSharedMemorySize, GEMM_SMEM);
    cudaFuncSetAttribute(gemm_mma<0, 0>, cudaFuncAttributeMaxDynamicSharedMemorySize, GEMM_SMEM);
    cudaFuncSetAttribute(gemm_mma<0, 1>, cudaFuncAttributeMaxDynamicSharedMemorySize, GEMM_SMEM);
    cudaFuncSetAttribute(gemm_mma<0, 2>, cudaFuncAttributeMaxDynamicSharedMemorySize, GEMM_SMEM);

    // conversions / weight prep
    split_flat<<<(512 * 1536 + 255) / 256, 256>>>(conv_w, 512 * 1536);
    awt_kernel<<<dim3(16, 8), dim3(32, 32)>>>(affine_w);
    bconst_kernel<<<192, 256>>>(conv_w, affine_b);
    biasrows_kernel<<<2, 256>>>(conv_b);
    split_bhl<<<(512 * 256 + 255) / 256, 256>>>(map_w, MWb, 256, 512 * 256);
    split_bhl<<<(int)(((long)NM1 * 256 + 255) / 256), 256>>>(enc_attn, EAb, 256, (long)NM1 * 256);
    sst_kernel<<<dim3(NS / 32, NC2 / 32, NB), dim3(32, 32)>>>(src_seq);
    gather_split<<<(int)(((long)NM1 * NE + 255) / 256), 256>>>(target, emb);

    // 0. fused weight: FW_tap[o,e] = conv_w[o,tap,:] @ affine_w[:,e]  (M=512,N=256,K'=1536)
    for (int tap = 0; tap < 3; tap++)
        gemm_mma<0, 3><<<dim3(1, 4, 1), 256, GEMM_SMEM>>>(
            CWh + tap * 512, CWl + tap * 512, 512, 1536, AWT, 0,
            nullptr, nullptr, 0, FWB + tap * 256, 512);

    // 1. fused conv on G: Y = im2col_E(G) @ FW^T + biasrows  (M=1023/b, N=512, K'=2304)
    gemm_mma<2, 5><<<dim3(2, 8, NB), 256, GEMM_SMEM>>>(
        Ghi, Glo, 768, 0, FWB, 0, BR, Y, 512, nullptr, NL);
    // 2. GLU
    glu_kernel<<<NM2, 256>>>();
    // 3. map: out = dec @ MW^T + b            (M=1023/b, N=512, K'=768)
    gemm_mma<0, 0><<<dim3(2, 8, NB), 256, GEMM_SMEM>>>(
        Dhi, Dlo, 256, 256, MWb, 0, map_b, out, 512, nullptr, NL);
    // 4. scores = dec @ enc^T (batched)       (N=1024, K'=768)
    gemm_mma<0, 1><<<dim3(4, 8, NB), 256, GEMM_SMEM>>>(
        Dhi, Dlo, 256, 256, EAb, (long)NS * 768, nullptr, SC, NS, nullptr, NL);
    // 5. softmax -> split attn
    softmax_rows_kernel<<<NM2, 256>>>();
    // 6. out += attn @ src_seq (batched)      (N=512, K'=3072)
    gemm_mma<0, 2><<<dim3(2, 8, NB), 256, GEMM_SMEM>>>(
        AThi, ATlo, 1024, 1024, SST, (long)NC2 * 3 * NS, nullptr, out, 512, nullptr, NL);
}

// round 6
// speedup vs baseline: 1.1658x; 1.1658x over previous
#include <cuda_runtime.h>
#include <cuda_bf16.h>
#include <cstdint>

#define NB   32
#define NL   1023
#define NS   1024
#define NH   256
#define NC2  512
#define NE   256
#define NM1  32768
#define NM2  32736

// ---------------- scratch ----------------------------------------------------
__device__ __nv_bfloat16 g_Ghi[NM1 * NE],  g_Glo[NM1 * NE];
__device__ float         g_Y  [NM2 * NC2];
__device__ __nv_bfloat16 g_Dhi[NM2 * NH],  g_Dlo[NM2 * NH];
__device__ float         g_SC [(long)NM2 * NS];
__device__ __nv_bfloat16 g_AThi[(long)NM2 * NS], g_ATlo[(long)NM2 * NS];
__device__ __nv_bfloat16 g_CWh[NC2 * 1536], g_CWl[NC2 * 1536];  // conv_w split flat
__device__ __nv_bfloat16 g_AWT[NE * 3 * NC2];                   // affine_w^T [h|l|h]
__device__ __nv_bfloat16 g_FWB[NC2 * 3 * 768];                  // fused weight [h|l|h]
__device__ __nv_bfloat16 g_MWb[NC2 * 3 * NH];
__device__ __nv_bfloat16 g_EAb[(long)NB * NS * 3 * NH];
__device__ __nv_bfloat16 g_SST[(long)NB * NC2 * 3 * NS];
__device__ float         g_BC [3 * NC2];
__device__ float         g_BR [3 * NC2];

// ---------------- helpers ----------------------------------------------------
__device__ __forceinline__ uint32_t smem_u32(const void* p) {
    uint32_t a;
    asm("{ .reg .u64 t; cvta.to.shared.u64 t, %1; cvt.u32.u64 %0, t; }" : "=r"(a) : "l"(p));
    return a;
}
__device__ __forceinline__ void cpasync16(uint32_t s, const void* g, bool pred) {
    int sz = pred ? 16 : 0;
    asm volatile("cp.async.cg.shared.global [%0], [%1], 16, %2;\n" :: "r"(s), "l"(g), "r"(sz));
}
__device__ __forceinline__ void cp_commit() { asm volatile("cp.async.commit_group;\n" ::: "memory"); }

__device__ __forceinline__ void ldm4(uint32_t* r, uint32_t a) {
    asm volatile("ldmatrix.sync.aligned.m8n8.x4.shared.b16 {%0,%1,%2,%3}, [%4];"
                 : "=r"(r[0]), "=r"(r[1]), "=r"(r[2]), "=r"(r[3]) : "r"(a));
}
__device__ __forceinline__ void mma16816(float* c, const uint32_t* a, const uint32_t* b) {
    asm volatile(
        "mma.sync.aligned.m16n8k16.row.col.f32.bf16.bf16.f32 "
        "{%0,%1,%2,%3}, {%4,%5,%6,%7}, {%8,%9}, {%0,%1,%2,%3};"
        : "+f"(c[0]), "+f"(c[1]), "+f"(c[2]), "+f"(c[3])
        : "r"(a[0]), "r"(a[1]), "r"(a[2]), "r"(a[3]), "r"(b[0]), "r"(b[1]));
}
__device__ __forceinline__ void split2(float v, __nv_bfloat16& h, __nv_bfloat16& l) {
    h = __float2bfloat16(v);
    l = __float2bfloat16(v - __bfloat162float(h));
}

// ---------------- conversion kernels ----------------------------------------
// dst[n, 3K] = [hi | lo | hi] from src[n, K], 2 elems/thread (K even)
__global__ void split_bhl(const float* __restrict__ src, __nv_bfloat16* __restrict__ dst,
                          int K, long total2) {   // total2 = total/2
    long gid = (long)blockIdx.x * blockDim.x + threadIdx.x;
    if (gid >= total2) return;
    long e2 = gid * 2;
    long n = e2 / K;
    int  k = (int)(e2 - n * K);
    float2 v = *(const float2*)(src + e2);
    __nv_bfloat16 h0, l0, h1, l1;
    split2(v.x, h0, l0); split2(v.y, h1, l1);
    __nv_bfloat162 hh; hh.x = h0; hh.y = h1;
    __nv_bfloat162 ll; ll.x = l0; ll.y = l1;
    long b0 = n * 3 * (long)K + k;
    *(__nv_bfloat162*)(dst + b0)         = hh;
    *(__nv_bfloat162*)(dst + b0 + K)     = ll;
    *(__nv_bfloat162*)(dst + b0 + 2 * K) = hh;
}

__global__ void split_flat(const float* __restrict__ src, long total2) {
    long gid = (long)blockIdx.x * blockDim.x + threadIdx.x;
    if (gid >= total2) return;
    float2 v = *(const float2*)(src + gid * 2);
    __nv_bfloat16 h0, l0, h1, l1;
    split2(v.x, h0, l0); split2(v.y, h1, l1);
    __nv_bfloat162 hh; hh.x = h0; hh.y = h1;
    __nv_bfloat162 ll; ll.x = l0; ll.y = l1;
    *(__nv_bfloat162*)(g_CWh + gid * 2) = hh;
    *(__nv_bfloat162*)(g_CWl + gid * 2) = ll;
}

__global__ void awt_kernel(const float* __restrict__ aw) {
    __shared__ float tile[32][33];
    int i0 = blockIdx.x * 32, e0 = blockIdx.y * 32;
    int tx = threadIdx.x, ty = threadIdx.y;
    tile[ty][tx] = aw[(i0 + ty) * NE + e0 + tx];
    __syncthreads();
    float v = tile[tx][ty];
    __nv_bfloat16 h, l; split2(v, h, l);
    long base = (long)(e0 + ty) * 1536 + i0 + tx;
    g_AWT[base] = h; g_AWT[base + 512] = l; g_AWT[base + 1024] = h;
}

__global__ void bconst_kernel(const float* __restrict__ cw, const float* __restrict__ ab) {
    int wid = (blockIdx.x * blockDim.x + threadIdx.x) >> 5;
    int lane = threadIdx.x & 31;
    if (wid >= 1536) return;
    int tap = wid / 512, o = wid % 512;
    const float* row = cw + (long)o * 1536 + tap * 512;
    float s = 0.f;
    for (int i = lane; i < 512; i += 32) s += row[i] * ab[i];
    #pragma unroll
    for (int off = 16; off > 0; off >>= 1) s += __shfl_xor_sync(~0u, s, off);
    if (lane == 0) g_BC[tap * 512 + o] = s;
}

__global__ void biasrows_kernel(const float* __restrict__ conv_b) {
    int o = blockIdx.x * blockDim.x + threadIdx.x;
    if (o >= 512) return;
    float b = conv_b[o];
    float c0 = g_BC[o], c1 = g_BC[512 + o], c2 = g_BC[1024 + o];
    g_BR[o]        = b + c2;
    g_BR[512 + o]  = b + c1 + c2;
    g_BR[1024 + o] = b + c0 + c1 + c2;
}

// 2 elems/thread
__global__ void gather_split(const int* __restrict__ target, const float* __restrict__ emb) {
    long gid = (long)blockIdx.x * blockDim.x + threadIdx.x;   // over NM1*128
    if (gid >= (long)NM1 * 128) return;
    int m = (int)(gid >> 7);
    int k = ((int)gid & 127) * 2;
    int b = m >> 10, t = m & 1023;
    int idx = target[t * NB + b];
    float2 v = *(const float2*)(emb + (long)idx * NE + k);
    __nv_bfloat16 h0, l0, h1, l1;
    split2(v.x, h0, l0); split2(v.y, h1, l1);
    __nv_bfloat162 hh; hh.x = h0; hh.y = h1;
    __nv_bfloat162 ll; ll.x = l0; ll.y = l1;
    *(__nv_bfloat162*)(g_Ghi + (long)m * NE + k) = hh;
    *(__nv_bfloat162*)(g_Glo + (long)m * NE + k) = ll;
}

__global__ void sst_kernel(const float* __restrict__ src) {
    __shared__ float tile[32][33];
    int b = blockIdx.z;
    int s0 = blockIdx.x * 32, d0 = blockIdx.y * 32;
    int tx = threadIdx.x, ty = threadIdx.y;
    tile[ty][tx] = src[((long)b * NS + s0 + ty) * NC2 + d0 + tx];
    __syncthreads();
    int d = d0 + ty, s = s0 + tx;
    float v = tile[tx][ty];
    __nv_bfloat16 h, l; split2(v, h, l);
    long base = ((long)b * NC2 + d) * (3 * NS) + s;
    g_SST[base] = h; g_SST[base + NS] = l; g_SST[base + 2 * NS] = h;
}

__global__ void glu_kernel() {
    int m = blockIdx.x;
    int h = threadIdx.x;
    float a = g_Y[(long)m * NC2 + h];
    float g = g_Y[(long)m * NC2 + NH + h];
    a = fmaxf(a, 0.f); g = fmaxf(g, 0.f);
    __shared__ float red[8];
    float v = g;
    #pragma unroll
    for (int o = 16; o > 0; o >>= 1) v = fmaxf(v, __shfl_xor_sync(~0u, v, o));
    if ((h & 31) == 0) red[h >> 5] = v;
    __syncthreads();
    float mx = red[0];
    #pragma unroll
    for (int i = 1; i < 8; i++) mx = fmaxf(mx, red[i]);
    float e = expf(g - mx);
    __syncthreads();
    v = e;
    #pragma unroll
    for (int o = 16; o > 0; o >>= 1) v += __shfl_xor_sync(~0u, v, o);
    if ((h & 31) == 0) red[h >> 5] = v;
    __syncthreads();
    float sum = 0.f;
    #pragma unroll
    for (int i = 0; i < 8; i++) sum += red[i];
    float dec = a * e / sum;
    __nv_bfloat16 hi, lo; split2(dec, hi, lo);
    g_Dhi[(long)m * NH + h] = hi;
    g_Dlo[(long)m * NH + h] = lo;
}

__global__ void softmax_rows_kernel() {
    int m = blockIdx.x;
    int h = threadIdx.x;
    const float* row = g_SC + (long)m * NS;
    float x0 = row[h], x1 = row[h + 256], x2 = row[h + 512], x3 = row[h + 768];
    __shared__ float red[8];
    float v = fmaxf(fmaxf(x0, x1), fmaxf(x2, x3));
    #pragma unroll
    for (int o = 16; o > 0; o >>= 1) v = fmaxf(v, __shfl_xor_sync(~0u, v, o));
    if ((h & 31) == 0) red[h >> 5] = v;
    __syncthreads();
    float mx = red[0];
    #pragma unroll
    for (int i = 1; i < 8; i++) mx = fmaxf(mx, red[i]);
    float e0 = expf(x0 - mx), e1 = expf(x1 - mx), e2 = expf(x2 - mx), e3 = expf(x3 - mx);
    __syncthreads();
    v = e0 + e1 + e2 + e3;
    #pragma unroll
    for (int o = 16; o > 0; o >>= 1) v += __shfl_xor_sync(~0u, v, o);
    if ((h & 31) == 0) red[h >> 5] = v;
    __syncthreads();
    float sum = 0.f;
    #pragma unroll
    for (int i = 0; i < 8; i++) sum += red[i];
    float inv = 1.f / sum;
    long base = (long)m * NS;
    #pragma unroll
    for (int q = 0; q < 4; q++) {
        float e = (q == 0 ? e0 : q == 1 ? e1 : q == 2 ? e2 : e3) * inv;
        __nv_bfloat16 hi, lo; split2(e, hi, lo);
        g_AThi[base + h + q * 256] = hi;
        g_ATlo[base + h + q * 256] = lo;
    }
}

// ---------------- mma.sync bf16 GEMM (R4 config: 128x128, occ 2) --------------
// C[M, N] = A'[M, 3K] * B'[N, 3K]^T ; A' logical [Ahi | Ahi | Alo], B' = [hi|lo|hi].
// BK=32, 4-stage cp.async, 256 thr (8 warps, 2x4 -> 64x32 warp tile).
// AMODE 0: rows (z*Mb + l) * lda + k.  AMODE 2 (fused conv on G): k -> (tap, e),
//          t = l-2+tap, read (z*1024+t)*256 + e; zero-fill t<0.
// EPI: 0 f32+bias1D, 1 f32, 2 f32 accumulate,
//      3 FW split write ([h|l|h] at +0/+768/+1536, ld 2304, no bias),
//      5 f32 + bias2D rows BR[min(l,2)].
#define GEMM_SMEM (4 * 16384)

template <int AMODE, int EPI>
__global__ __launch_bounds__(256, 2)
void gemm_mma(const __nv_bfloat16* __restrict__ Ahi, const __nv_bfloat16* __restrict__ Alo,
              int KB, int lda, const __nv_bfloat16* __restrict__ Bm, long bBatch,
              const float* __restrict__ bias,
              float* __restrict__ C, int cLd,
              __nv_bfloat16* __restrict__ Ohi,
              int Mb) {
    extern __shared__ char smem[];
    const uint32_t sb = smem_u32(smem);
    const int tid = threadIdx.x;
    const int z  = blockIdx.z;
    const int l0 = blockIdx.y * 128;
    const int n0 = blockIdx.x * 128;
    const int Kp = 3 * KB;
    const int NK = Kp / 32;
    const __nv_bfloat16* Bb = Bm + (long)z * bBatch;

    auto load_tile = [&](int kt, int st) {
        const int k0 = kt * 32;
        const int seg = k0 / KB;
        const int rem0 = k0 - seg * KB;
        const __nv_bfloat16* Ab = (seg < 2) ? Ahi : Alo;
        const uint32_t sA = sb + st * 16384;
        const uint32_t sB = sA + 8192;
        #pragma unroll
        for (int i = 0; i < 2; i++) {
            int c = tid + i * 256;          // 0..511
            int m = c >> 2, kc = c & 3;
            int l = l0 + m;
            long g; bool ok;
            if (AMODE == 0) {
                ok = (l < Mb);
                g = ((long)z * Mb + l) * (long)lda + rem0 + kc * 8;
            } else {                         // fused conv on G
                int tap = rem0 >> 8;
                int e = (rem0 & 255) + kc * 8;
                int t = l - 2 + tap;
                ok = (l < Mb) && (t >= 0);
                g = ((long)z * 1024 + t) * 256 + e;
            }
            cpasync16(sA + m * 64 + ((uint32_t)(kc ^ (m & 3)) << 4), Ab + (ok ? g : 0), ok);
        }
        #pragma unroll
        for (int i = 0; i < 2; i++) {
            int c = tid + i * 256;
            int n = c >> 2, kc = c & 3;
            cpasync16(sB + n * 64 + ((uint32_t)(kc ^ (n & 3)) << 4),
                      Bb + (long)(n0 + n) * Kp + k0 + kc * 8, true);
        }
        cp_commit();
    };

    float acc[4][4][4];
    #pragma unroll
    for (int i = 0; i < 4; i++)
        #pragma unroll
        for (int j = 0; j < 4; j++)
            #pragma unroll
            for (int q = 0; q < 4; q++) acc[i][j][q] = 0.f;

    const int w = tid >> 5, lid = tid & 31;
    const int wm = w >> 2, wn = w & 3;          // warp grid 2 x 4
    const int rl = wm * 64 + (lid & 15);        // A ldmatrix row
    const int aC = lid >> 4;                    // A k-chunk bit
    const int nl = wn * 32 + ((lid >> 4) << 3) + (lid & 7);  // B ldmatrix row
    const int bC = (lid >> 3) & 1;              // B k-chunk bit

    load_tile(0, 0); load_tile(1, 1); load_tile(2, 2);

    for (int kt = 0; kt < NK; kt++) {
        const int st = kt & 3;
        asm volatile("cp.async.wait_group 2;\n" ::: "memory");
        __syncthreads();
        if (kt + 3 < NK) load_tile(kt + 3, (kt + 3) & 3);
        else cp_commit();

        const uint32_t sA = sb + st * 16384;
        const uint32_t sB = sA + 8192;

        // prefetch ALL A fragments for this kt (both k-halves) up front
        uint32_t a[2][4][4];
        #pragma unroll
        for (int ks = 0; ks < 2; ks++)
            #pragma unroll
            for (int i = 0; i < 4; i++) {
                int r = rl + i * 16;
                ldm4(a[ks][i], sA + r * 64 + ((uint32_t)((ks * 2 + aC) ^ (r & 3)) << 4));
            }
        // B for ks=0
        uint32_t b0[4][2];
        #pragma unroll
        for (int jj = 0; jj < 2; jj++) {
            int n = nl + jj * 16;
            uint32_t t[4];
            ldm4(t, sB + n * 64 + ((uint32_t)((0 + bC) ^ (n & 3)) << 4));
            b0[jj * 2][0] = t[0]; b0[jj * 2][1] = t[1];
            b0[jj * 2 + 1][0] = t[2]; b0[jj * 2 + 1][1] = t[3];
        }
        // B for ks=1 (hoisted above ks=0 MMAs to overlap LDSM with HMMA)
        uint32_t b1[4][2];
        #pragma unroll
        for (int jj = 0; jj < 2; jj++) {
            int n = nl + jj * 16;
            uint32_t t[4];
            ldm4(t, sB + n * 64 + ((uint32_t)((2 + bC) ^ (n & 3)) << 4));
            b1[jj * 2][0] = t[0]; b1[jj * 2][1] = t[1];
            b1[jj * 2 + 1][0] = t[2]; b1[jj * 2 + 1][1] = t[3];
        }
        #pragma unroll
        for (int i = 0; i < 4; i++)
            #pragma unroll
            for (int j = 0; j < 4; j++)
                mma16816(acc[i][j], a[0][i], b0[j]);
        #pragma unroll
        for (int i = 0; i < 4; i++)
            #pragma unroll
            for (int j = 0; j < 4; j++)
                mma16816(acc[i][j], a[1][i], b1[j]);
    }

    // ---------------- epilogue ----------------
    const int g  = lid >> 2, t4 = lid & 3;
    #pragma unroll
    for (int i = 0; i < 4; i++) {
        #pragma unroll
        for (int h = 0; h < 2; h++) {
            int row = l0 + wm * 64 + i * 16 + g + h * 8;
            if (row >= Mb) continue;
            long grow = (long)z * Mb + row;
            #pragma unroll
            for (int j = 0; j < 4; j++) {
                int col = n0 + wn * 32 + j * 8 + 2 * t4;
                float v0 = acc[i][j][h * 2 + 0];
                float v1 = acc[i][j][h * 2 + 1];
                if (EPI == 0) { v0 += bias[col]; v1 += bias[col + 1]; }
                if (EPI == 5) {
                    int jb = (row < 2) ? row : 2;
                    v0 += bias[jb * 512 + col]; v1 += bias[jb * 512 + col + 1];
                }
                if (EPI == 3) {
                    __nv_bfloat16 h0, lb0, h1, lb1;
                    split2(v0, h0, lb0); split2(v1, h1, lb1);
                    __nv_bfloat162 hh; hh.x = h0; hh.y = h1;
                    __nv_bfloat162 ll; ll.x = lb0; ll.y = lb1;
                    long base = grow * 2304 + col;
                    *(__nv_bfloat162*)(Ohi + base)        = hh;
                    *(__nv_bfloat162*)(Ohi + base + 768)  = ll;
                    *(__nv_bfloat162*)(Ohi + base + 1536) = hh;
                } else {
                    float* cp = C + grow * (long)cLd + col;
                    if (EPI == 2) { v0 += cp[0]; v1 += cp[1]; }
                    float2 r; r.x = v0; r.y = v1;
                    *(float2*)cp = r;
                }
            }
        }
    }
}

// ---------------- launcher ---------------------------------------------------
extern "C" void kernel_launch(void* const* d_in, const int* in_sizes, int n_in,
                              void* d_out, int out_size) {
    const int*   target   = (const int*)d_in[1];
    const float* enc_attn = (const float*)d_in[2];
    const float* src_seq  = (const float*)d_in[3];
    const float* emb      = (const float*)d_in[4];
    const float* affine_w = (const float*)d_in[5];
    const float* affine_b = (const float*)d_in[6];
    const float* conv_w   = (const float*)d_in[7];
    const float* conv_b   = (const float*)d_in[8];
    const float* map_w    = (const float*)d_in[9];
    const float* map_b    = (const float*)d_in[10];
    float* out = (float*)d_out;

    __nv_bfloat16 *Ghi, *Glo, *Dhi, *Dlo, *AThi, *ATlo, *CWh, *CWl, *AWT, *FWB, *MWb, *EAb, *SST;
    float *Y, *SC, *BR;
    cudaGetSymbolAddress((void**)&Ghi, g_Ghi);   cudaGetSymbolAddress((void**)&Glo, g_Glo);
    cudaGetSymbolAddress((void**)&Y,   g_Y);
    cudaGetSymbolAddress((void**)&Dhi, g_Dhi);   cudaGetSymbolAddress((void**)&Dlo, g_Dlo);
    cudaGetSymbolAddress((void**)&SC,  g_SC);
    cudaGetSymbolAddress((void**)&AThi, g_AThi); cudaGetSymbolAddress((void**)&ATlo, g_ATlo);
    cudaGetSymbolAddress((void**)&CWh, g_CWh);   cudaGetSymbolAddress((void**)&CWl, g_CWl);
    cudaGetSymbolAddress((void**)&AWT, g_AWT);   cudaGetSymbolAddress((void**)&FWB, g_FWB);
    cudaGetSymbolAddress((void**)&MWb, g_MWb);   cudaGetSymbolAddress((void**)&EAb, g_EAb);
    cudaGetSymbolAddress((void**)&SST, g_SST);   cudaGetSymbolAddress((void**)&BR,  g_BR);

    cudaFuncSetAttribute(gemm_mma<0, 3>, cudaFuncAttributeMaxDynamicSharedMemorySize, GEMM_SMEM);
    cudaFuncSetAttribute(gemm_mma<2, 5>, cudaFuncAttributeMaxDynamicSharedMemorySize, GEMM_SMEM);
    cudaFuncSetAttribute(gemm_mma<0, 0>, cudaFuncAttributeMaxDynamicSharedMemorySize, GEMM_SMEM);
    cudaFuncSetAttribute(gemm_mma<0, 1>, cudaFuncAttributeMaxDynamicSharedMemorySize, GEMM_SMEM);
    cudaFuncSetAttribute(gemm_mma<0, 2>, cudaFuncAttributeMaxDynamicSharedMemorySize, GEMM_SMEM);

    // conversions / weight prep
    split_flat<<<(512 * 1536 / 2 + 255) / 256, 256>>>(conv_w, 512 * 1536 / 2);
    awt_kernel<<<dim3(16, 8), dim3(32, 32)>>>(affine_w);
    bconst_kernel<<<192, 256>>>(conv_w, affine_b);
    biasrows_kernel<<<2, 256>>>(conv_b);
    split_bhl<<<(512 * 256 / 2 + 255) / 256, 256>>>(map_w, MWb, 256, 512 * 256 / 2);
    split_bhl<<<(int)(((long)NM1 * 128 + 255) / 256), 256>>>(enc_attn, EAb, 256, (long)NM1 * 128);
    sst_kernel<<<dim3(NS / 32, NC2 / 32, NB), dim3(32, 32)>>>(src_seq);
    gather_split<<<(int)(((long)NM1 * 128 + 255) / 256), 256>>>(target, emb);

    // 0. fused weight: FW_tap[o,e] = conv_w[o,tap,:] @ affine_w[:,e]  (M=512,N=256,K'=1536)
    for (int tap = 0; tap < 3; tap++)
        gemm_mma<0, 3><<<dim3(2, 4, 1), 256, GEMM_SMEM>>>(
            CWh + tap * 512, CWl + tap * 512, 512, 1536, AWT, 0,
            nullptr, nullptr, 0, FWB + tap * 256, 512);

    // 1. fused conv on G: Y = im2col_E(G) @ FW^T + biasrows  (M=1023/b, N=512, K'=2304)
    gemm_mma<2, 5><<<dim3(4, 8, NB), 256, GEMM_SMEM>>>(
        Ghi, Glo, 768, 0, FWB, 0, BR, Y, 512, nullptr, NL);
    // 2. GLU
    glu_kernel<<<NM2, 256>>>();
    // 3. map: out = dec @ MW^T + b            (M=1023/b, N=512, K'=768)
    gemm_mma<0, 0><<<dim3(4, 8, NB), 256, GEMM_SMEM>>>(
        Dhi, Dlo, 256, 256, MWb, 0, map_b, out, 512, nullptr, NL);
    // 4. scores = dec @ enc^T (batched)       (N=1024, K'=768)
    gemm_mma<0, 1><<<dim3(8, 8, NB), 256, GEMM_SMEM>>>(
        Dhi, Dlo, 256, 256, EAb, (long)NS * 768, nullptr, SC, NS, nullptr, NL);
    // 5. softmax -> split attn
    softmax_rows_kernel<<<NM2, 256>>>();
    // 6. out += attn @ src_seq (batched)      (N=512, K'=3072)
    gemm_mma<0, 2><<<dim3(4, 8, NB), 256, GEMM_SMEM>>>(
        AThi, ATlo, 1024, 1024, SST, (long)NC2 * 3 * NS, nullptr, out, 512, nullptr, NL);
}

// round 7
// speedup vs baseline: 1.6178x; 1.3877x over previous
#include <cuda_runtime.h>
#include <cuda_fp16.h>
#include <cstdint>

#define NB   32
#define NL   1023
#define NS   1024
#define NH   256
#define NC2  512
#define NE   256
#define NM1  32768
#define NM2  32736

// ---------------- scratch ----------------------------------------------------
__device__ __half g_Gh [NM1 * NE];                 // embeddings, single fp16 limb
__device__ float  g_Y  [NM2 * NC2];
__device__ __half g_Dh [NM2 * NH];                 // dec_attn, single limb
__device__ float  g_SC [(long)NM2 * NS];
__device__ __half g_ATh[(long)NM2 * NS];           // attn probs, single limb
__device__ __half g_CWh[NC2 * 1536], g_CWl[NC2 * 1536];  // conv_w 2-limb flat
__device__ __half g_AWT[NE * 3 * NC2];             // affine_w^T [h|l|h] (3-seg)
__device__ __half g_FWB[NC2 * 2 * 768];            // fused weight [hi|lo]
__device__ __half g_MWb[NC2 * 2 * NH];             // map_w [hi|lo]
__device__ __half g_EAb[(long)NB * NS * 2 * NH];   // enc_attn [hi|lo]
__device__ __half g_SST[(long)NB * NC2 * 2 * NS];  // src_seq^T [hi|lo]
__device__ float  g_BC [3 * NC2];
__device__ float  g_BR [3 * NC2];

// ---------------- helpers ----------------------------------------------------
__device__ __forceinline__ uint32_t smem_u32(const void* p) {
    uint32_t a;
    asm("{ .reg .u64 t; cvta.to.shared.u64 t, %1; cvt.u32.u64 %0, t; }" : "=r"(a) : "l"(p));
    return a;
}
__device__ __forceinline__ void cpasync16(uint32_t s, const void* g, bool pred) {
    int sz = pred ? 16 : 0;
    asm volatile("cp.async.cg.shared.global [%0], [%1], 16, %2;\n" :: "r"(s), "l"(g), "r"(sz));
}
__device__ __forceinline__ void cp_commit() { asm volatile("cp.async.commit_group;\n" ::: "memory"); }

__device__ __forceinline__ void ldm4(uint32_t* r, uint32_t a) {
    asm volatile("ldmatrix.sync.aligned.m8n8.x4.shared.b16 {%0,%1,%2,%3}, [%4];"
                 : "=r"(r[0]), "=r"(r[1]), "=r"(r[2]), "=r"(r[3]) : "r"(a));
}
__device__ __forceinline__ void mma16816(float* c, const uint32_t* a, const uint32_t* b) {
    asm volatile(
        "mma.sync.aligned.m16n8k16.row.col.f32.f16.f16.f32 "
        "{%0,%1,%2,%3}, {%4,%5,%6,%7}, {%8,%9}, {%0,%1,%2,%3};"
        : "+f"(c[0]), "+f"(c[1]), "+f"(c[2]), "+f"(c[3])
        : "r"(a[0]), "r"(a[1]), "r"(a[2]), "r"(a[3]), "r"(b[0]), "r"(b[1]));
}
__device__ __forceinline__ void split2(float v, __half& h, __half& l) {
    h = __float2half(v);
    l = __float2half(v - __half2float(h));
}

// ---------------- conversion kernels ----------------------------------------
// dst[n, 2K] = [hi | lo] from src[n, K], 2 elems/thread
__global__ void split_hl(const float* __restrict__ src, __half* __restrict__ dst,
                         int K, long total2) {
    long gid = (long)blockIdx.x * blockDim.x + threadIdx.x;
    if (gid >= total2) return;
    long e2 = gid * 2;
    long n = e2 / K;
    int  k = (int)(e2 - n * K);
    float2 v = *(const float2*)(src + e2);
    __half h0, l0, h1, l1;
    split2(v.x, h0, l0); split2(v.y, h1, l1);
    __half2 hh; hh.x = h0; hh.y = h1;
    __half2 ll; ll.x = l0; ll.y = l1;
    long b0 = n * 2 * (long)K + k;
    *(__half2*)(dst + b0)     = hh;
    *(__half2*)(dst + b0 + K) = ll;
}

__global__ void split_flat(const float* __restrict__ src, long total2) {
    long gid = (long)blockIdx.x * blockDim.x + threadIdx.x;
    if (gid >= total2) return;
    float2 v = *(const float2*)(src + gid * 2);
    __half h0, l0, h1, l1;
    split2(v.x, h0, l0); split2(v.y, h1, l1);
    __half2 hh; hh.x = h0; hh.y = h1;
    __half2 ll; ll.x = l0; ll.y = l1;
    *(__half2*)(g_CWh + gid * 2) = hh;
    *(__half2*)(g_CWl + gid * 2) = ll;
}

// affine_w [512(i), 256(e)] -> AWT[e, [hi(512)|lo|hi]] (3-seg B for FW precompute)
__global__ void awt_kernel(const float* __restrict__ aw) {
    __shared__ float tile[32][33];
    int i0 = blockIdx.x * 32, e0 = blockIdx.y * 32;
    int tx = threadIdx.x, ty = threadIdx.y;
    tile[ty][tx] = aw[(i0 + ty) * NE + e0 + tx];
    __syncthreads();
    float v = tile[tx][ty];
    __half h, l; split2(v, h, l);
    long base = (long)(e0 + ty) * 1536 + i0 + tx;
    g_AWT[base] = h; g_AWT[base + 512] = l; g_AWT[base + 1024] = h;
}

__global__ void bconst_kernel(const float* __restrict__ cw, const float* __restrict__ ab) {
    int wid = (blockIdx.x * blockDim.x + threadIdx.x) >> 5;
    int lane = threadIdx.x & 31;
    if (wid >= 1536) return;
    int tap = wid / 512, o = wid % 512;
    const float* row = cw + (long)o * 1536 + tap * 512;
    float s = 0.f;
    for (int i = lane; i < 512; i += 32) s += row[i] * ab[i];
    #pragma unroll
    for (int off = 16; off > 0; off >>= 1) s += __shfl_xor_sync(~0u, s, off);
    if (lane == 0) g_BC[tap * 512 + o] = s;
}

__global__ void biasrows_kernel(const float* __restrict__ conv_b) {
    int o = blockIdx.x * blockDim.x + threadIdx.x;
    if (o >= 512) return;
    float b = conv_b[o];
    float c0 = g_BC[o], c1 = g_BC[512 + o], c2 = g_BC[1024 + o];
    g_BR[o]        = b + c2;
    g_BR[512 + o]  = b + c1 + c2;
    g_BR[1024 + o] = b + c0 + c1 + c2;
}

// gather + plain fp16 cast, 2 elems/thread
__global__ void gather_h(const int* __restrict__ target, const float* __restrict__ emb) {
    long gid = (long)blockIdx.x * blockDim.x + threadIdx.x;   // over NM1*128
    if (gid >= (long)NM1 * 128) return;
    int m = (int)(gid >> 7);
    int k = ((int)gid & 127) * 2;
    int b = m >> 10, t = m & 1023;
    int idx = target[t * NB + b];
    float2 v = *(const float2*)(emb + (long)idx * NE + k);
    __half2 hh; hh.x = __float2half(v.x); hh.y = __float2half(v.y);
    *(__half2*)(g_Gh + (long)m * NE + k) = hh;
}

// src_seq (b,s,d) f32 -> SST (b, d, [hi(1024)|lo]) fp16
__global__ void sst_kernel(const float* __restrict__ src) {
    __shared__ float tile[32][33];
    int b = blockIdx.z;
    int s0 = blockIdx.x * 32, d0 = blockIdx.y * 32;
    int tx = threadIdx.x, ty = threadIdx.y;
    tile[ty][tx] = src[((long)b * NS + s0 + ty) * NC2 + d0 + tx];
    __syncthreads();
    int d = d0 + ty, s = s0 + tx;
    float v = tile[tx][ty];
    __half h, l; split2(v, h, l);
    long base = ((long)b * NC2 + d) * (2 * NS) + s;
    g_SST[base] = h; g_SST[base + NS] = l;
}

__global__ void glu_kernel() {
    int m = blockIdx.x;
    int h = threadIdx.x;
    float a = g_Y[(long)m * NC2 + h];
    float g = g_Y[(long)m * NC2 + NH + h];
    a = fmaxf(a, 0.f); g = fmaxf(g, 0.f);
    __shared__ float red[8];
    float v = g;
    #pragma unroll
    for (int o = 16; o > 0; o >>= 1) v = fmaxf(v, __shfl_xor_sync(~0u, v, o));
    if ((h & 31) == 0) red[h >> 5] = v;
    __syncthreads();
    float mx = red[0];
    #pragma unroll
    for (int i = 1; i < 8; i++) mx = fmaxf(mx, red[i]);
    float e = expf(g - mx);
    __syncthreads();
    v = e;
    #pragma unroll
    for (int o = 16; o > 0; o >>= 1) v += __shfl_xor_sync(~0u, v, o);
    if ((h & 31) == 0) red[h >> 5] = v;
    __syncthreads();
    float sum = 0.f;
    #pragma unroll
    for (int i = 0; i < 8; i++) sum += red[i];
    g_Dh[(long)m * NH + h] = __float2half(a * e / sum);
}

__global__ void softmax_rows_kernel() {
    int m = blockIdx.x;
    int h = threadIdx.x;
    const float* row = g_SC + (long)m * NS;
    float x0 = row[h], x1 = row[h + 256], x2 = row[h + 512], x3 = row[h + 768];
    __shared__ float red[8];
    float v = fmaxf(fmaxf(x0, x1), fmaxf(x2, x3));
    #pragma unroll
    for (int o = 16; o > 0; o >>= 1) v = fmaxf(v, __shfl_xor_sync(~0u, v, o));
    if ((h & 31) == 0) red[h >> 5] = v;
    __syncthreads();
    float mx = red[0];
    #pragma unroll
    for (int i = 1; i < 8; i++) mx = fmaxf(mx, red[i]);
    float e0 = expf(x0 - mx), e1 = expf(x1 - mx), e2 = expf(x2 - mx), e3 = expf(x3 - mx);
    __syncthreads();
    v = e0 + e1 + e2 + e3;
    #pragma unroll
    for (int o = 16; o > 0; o >>= 1) v += __shfl_xor_sync(~0u, v, o);
    if ((h & 31) == 0) red[h >> 5] = v;
    __syncthreads();
    float sum = 0.f;
    #pragma unroll
    for (int i = 0; i < 8; i++) sum += red[i];
    float inv = 1.f / sum;
    long base = (long)m * NS;
    g_ATh[base + h]       = __float2half(e0 * inv);
    g_ATh[base + h + 256] = __float2half(e1 * inv);
    g_ATh[base + h + 512] = __float2half(e2 * inv);
    g_ATh[base + h + 768] = __float2half(e3 * inv);
}

// ---------------- mma.sync fp16 GEMM (128x128, occ 2, R4 loop) ---------------
// NSEG=2: C = A[M,K] * (Bhi+Blo)[N,2K]^T (A single limb, read same for both segs).
// NSEG=3: C = [Ahi|Ahi|Alo] * [Bh|Bl|Bh]^T (FW precompute, 2^-22 accurate).
// AMODE 0: rows (z*Mb + l) * lda + k.  AMODE 2 (fused conv on G): k -> (tap, e),
//          t = l-2+tap, read (z*1024+t)*256 + e; zero-fill t<0.
// EPI: 0 f32+bias1D, 1 f32, 2 f32 accumulate,
//      3 fp16 [hi|lo] write (at +0/+768, ld 1536, no bias),
//      5 f32 + bias2D rows BR[min(l,2)].
#define GEMM_SMEM (4 * 16384)

template <int AMODE, int EPI, int NSEG>
__global__ __launch_bounds__(256, 2)
void gemm_mma(const __half* __restrict__ Ahi, const __half* __restrict__ Alo,
              int KB, int lda, const __half* __restrict__ Bm, long bBatch,
              const float* __restrict__ bias,
              float* __restrict__ C, int cLd,
              __half* __restrict__ Ohi,
              int Mb) {
    extern __shared__ char smem[];
    const uint32_t sb = smem_u32(smem);
    const int tid = threadIdx.x;
    const int z  = blockIdx.z;
    const int l0 = blockIdx.y * 128;
    const int n0 = blockIdx.x * 128;
    const int Kp = NSEG * KB;
    const int NK = Kp / 32;
    const __half* Bb = Bm + (long)z * bBatch;

    auto load_tile = [&](int kt, int st) {
        const int k0 = kt * 32;
        const int seg = k0 / KB;
        const int rem0 = k0 - seg * KB;
        const __half* Ab = (NSEG == 3 && seg == 2) ? Alo : Ahi;
        const uint32_t sA = sb + st * 16384;
        const uint32_t sB = sA + 8192;
        #pragma unroll
        for (int i = 0; i < 2; i++) {
            int c = tid + i * 256;          // 0..511
            int m = c >> 2, kc = c & 3;
            int l = l0 + m;
            long g; bool ok;
            if (AMODE == 0) {
                ok = (l < Mb);
                g = ((long)z * Mb + l) * (long)lda + rem0 + kc * 8;
            } else {                         // fused conv on G
                int tap = rem0 >> 8;
                int e = (rem0 & 255) + kc * 8;
                int t = l - 2 + tap;
                ok = (l < Mb) && (t >= 0);
                g = ((long)z * 1024 + t) * 256 + e;
            }
            cpasync16(sA + m * 64 + ((uint32_t)(kc ^ (m & 3)) << 4), Ab + (ok ? g : 0), ok);
        }
        #pragma unroll
        for (int i = 0; i < 2; i++) {
            int c = tid + i * 256;
            int n = c >> 2, kc = c & 3;
            cpasync16(sB + n * 64 + ((uint32_t)(kc ^ (n & 3)) << 4),
                      Bb + (long)(n0 + n) * Kp + k0 + kc * 8, true);
        }
        cp_commit();
    };

    float acc[4][4][4];
    #pragma unroll
    for (int i = 0; i < 4; i++)
        #pragma unroll
        for (int j = 0; j < 4; j++)
            #pragma unroll
            for (int q = 0; q < 4; q++) acc[i][j][q] = 0.f;

    const int w = tid >> 5, lid = tid & 31;
    const int wm = w >> 2, wn = w & 3;
    const int rl = wm * 64 + (lid & 15);
    const int aC = lid >> 4;
    const int nl = wn * 32 + ((lid >> 4) << 3) + (lid & 7);
    const int bC = (lid >> 3) & 1;

    load_tile(0, 0); load_tile(1, 1); load_tile(2, 2);

    for (int kt = 0; kt < NK; kt++) {
        const int st = kt & 3;
        asm volatile("cp.async.wait_group 2;\n" ::: "memory");
        __syncthreads();
        if (kt + 3 < NK) load_tile(kt + 3, (kt + 3) & 3);
        else cp_commit();

        const uint32_t sA = sb + st * 16384;
        const uint32_t sB = sA + 8192;
        #pragma unroll
        for (int ks = 0; ks < 2; ks++) {
            uint32_t a[4][4];
            #pragma unroll
            for (int i = 0; i < 4; i++) {
                int r = rl + i * 16;
                ldm4(a[i], sA + r * 64 + ((uint32_t)((ks * 2 + aC) ^ (r & 3)) << 4));
            }
            uint32_t b[4][2];
            #pragma unroll
            for (int jj = 0; jj < 2; jj++) {
                int n = nl + jj * 16;
                uint32_t t[4];
                ldm4(t, sB + n * 64 + ((uint32_t)((ks * 2 + bC) ^ (n & 3)) << 4));
                b[jj * 2][0] = t[0]; b[jj * 2][1] = t[1];
                b[jj * 2 + 1][0] = t[2]; b[jj * 2 + 1][1] = t[3];
            }
            #pragma unroll
            for (int i = 0; i < 4; i++)
                #pragma unroll
                for (int j = 0; j < 4; j++)
                    mma16816(acc[i][j], a[i], b[j]);
        }
    }

    // ---------------- epilogue ----------------
    const int g  = lid >> 2, t4 = lid & 3;
    #pragma unroll
    for (int i = 0; i < 4; i++) {
        #pragma unroll
        for (int h = 0; h < 2; h++) {
            int row = l0 + wm * 64 + i * 16 + g + h * 8;
            if (row >= Mb) continue;
            long grow = (long)z * Mb + row;
            #pragma unroll
            for (int j = 0; j < 4; j++) {
                int col = n0 + wn * 32 + j * 8 + 2 * t4;
                float v0 = acc[i][j][h * 2 + 0];
                float v1 = acc[i][j][h * 2 + 1];
                if (EPI == 0) { v0 += bias[col]; v1 += bias[col + 1]; }
                if (EPI == 5) {
                    int jb = (row < 2) ? row : 2;
                    v0 += bias[jb * 512 + col]; v1 += bias[jb * 512 + col + 1];
                }
                if (EPI == 3) {
                    __half h0, lb0, h1, lb1;
                    split2(v0, h0, lb0); split2(v1, h1, lb1);
                    __half2 hh; hh.x = h0; hh.y = h1;
                    __half2 ll; ll.x = lb0; ll.y = lb1;
                    long base = grow * 1536 + col;
                    *(__half2*)(Ohi + base)       = hh;
                    *(__half2*)(Ohi + base + 768) = ll;
                } else {
                    float* cp = C + grow * (long)cLd + col;
                    if (EPI == 2) { v0 += cp[0]; v1 += cp[1]; }
                    float2 r; r.x = v0; r.y = v1;
                    *(float2*)cp = r;
                }
            }
        }
    }
}

// ---------------- launcher ---------------------------------------------------
extern "C" void kernel_launch(void* const* d_in, const int* in_sizes, int n_in,
                              void* d_out, int out_size) {
    const int*   target   = (const int*)d_in[1];
    const float* enc_attn = (const float*)d_in[2];
    const float* src_seq  = (const float*)d_in[3];
    const float* emb      = (const float*)d_in[4];
    const float* affine_w = (const float*)d_in[5];
    const float* affine_b = (const float*)d_in[6];
    const float* conv_w   = (const float*)d_in[7];
    const float* conv_b   = (const float*)d_in[8];
    const float* map_w    = (const float*)d_in[9];
    const float* map_b    = (const float*)d_in[10];
    float* out = (float*)d_out;

    __half *Gh, *Dh, *ATh, *CWh, *CWl, *AWT, *FWB, *MWb, *EAb, *SST;
    float *Y, *SC, *BR;
    cudaGetSymbolAddress((void**)&Gh,  g_Gh);
    cudaGetSymbolAddress((void**)&Y,   g_Y);
    cudaGetSymbolAddress((void**)&Dh,  g_Dh);
    cudaGetSymbolAddress((void**)&SC,  g_SC);
    cudaGetSymbolAddress((void**)&ATh, g_ATh);
    cudaGetSymbolAddress((void**)&CWh, g_CWh);   cudaGetSymbolAddress((void**)&CWl, g_CWl);
    cudaGetSymbolAddress((void**)&AWT, g_AWT);   cudaGetSymbolAddress((void**)&FWB, g_FWB);
    cudaGetSymbolAddress((void**)&MWb, g_MWb);   cudaGetSymbolAddress((void**)&EAb, g_EAb);
    cudaGetSymbolAddress((void**)&SST, g_SST);   cudaGetSymbolAddress((void**)&BR,  g_BR);

    cudaFuncSetAttribute(gemm_mma<0, 3, 3>, cudaFuncAttributeMaxDynamicSharedMemorySize, GEMM_SMEM);
    cudaFuncSetAttribute(gemm_mma<2, 5, 2>, cudaFuncAttributeMaxDynamicSharedMemorySize, GEMM_SMEM);
    cudaFuncSetAttribute(gemm_mma<0, 0, 2>, cudaFuncAttributeMaxDynamicSharedMemorySize, GEMM_SMEM);
    cudaFuncSetAttribute(gemm_mma<0, 1, 2>, cudaFuncAttributeMaxDynamicSharedMemorySize, GEMM_SMEM);
    cudaFuncSetAttribute(gemm_mma<0, 2, 2>, cudaFuncAttributeMaxDynamicSharedMemorySize, GEMM_SMEM);

    // conversions / weight prep
    split_flat<<<(512 * 1536 / 2 + 255) / 256, 256>>>(conv_w, 512 * 1536 / 2);
    awt_kernel<<<dim3(16, 8), dim3(32, 32)>>>(affine_w);
    bconst_kernel<<<192, 256>>>(conv_w, affine_b);
    biasrows_kernel<<<2, 256>>>(conv_b);
    split_hl<<<(512 * 256 / 2 + 255) / 256, 256>>>(map_w, MWb, 256, 512 * 256 / 2);
    split_hl<<<(int)(((long)NM1 * 128 + 255) / 256), 256>>>(enc_attn, EAb, 256, (long)NM1 * 128);
    sst_kernel<<<dim3(NS / 32, NC2 / 32, NB), dim3(32, 32)>>>(src_seq);
    gather_h<<<(int)(((long)NM1 * 128 + 255) / 256), 256>>>(target, emb);

    // 0. fused weight (3-term, 2^-22): FW_tap[o,e] = conv_w[o,tap,:] @ affine_w[:,e]
    for (int tap = 0; tap < 3; tap++)
        gemm_mma<0, 3, 3><<<dim3(2, 4, 1), 256, GEMM_SMEM>>>(
            CWh + tap * 512, CWl + tap * 512, 512, 1536, AWT, 0,
            nullptr, nullptr, 0, FWB + tap * 256, 512);

    // 1. fused conv on G: Y = im2col_E(G) @ FW^T + biasrows  (M=1023/b, N=512, K'=1536)
    gemm_mma<2, 5, 2><<<dim3(4, 8, NB), 256, GEMM_SMEM>>>(
        Gh, nullptr, 768, 0, FWB, 0, BR, Y, 512, nullptr, NL);
    // 2. GLU
    glu_kernel<<<NM2, 256>>>();
    // 3. map: out = dec @ MW^T + b            (M=1023/b, N=512, K'=512)
    gemm_mma<0, 0, 2><<<dim3(4, 8, NB), 256, GEMM_SMEM>>>(
        Dh, nullptr, 256, 256, MWb, 0, map_b, out, 512, nullptr, NL);
    // 4. scores = dec @ enc^T (batched)       (N=1024, K'=512)
    gemm_mma<0, 1, 2><<<dim3(8, 8, NB), 256, GEMM_SMEM>>>(
        Dh, nullptr, 256, 256, EAb, (long)NS * 512, nullptr, SC, NS, nullptr, NL);
    // 5. softmax -> fp16 attn probs
    softmax_rows_kernel<<<NM2, 256>>>();
    // 6. out += attn @ src_seq (batched)      (N=512, K'=2048)
    gemm_mma<0, 2, 2><<<dim3(4, 8, NB), 256, GEMM_SMEM>>>(
        ATh, nullptr, 1024, 1024, SST, (long)NC2 * 2 * NS, nullptr, out, 512, nullptr, NL);
}

// round 8
// speedup vs baseline: 2.3691x; 1.4644x over previous
#include <cuda_runtime.h>
#include <cuda_fp16.h>
#include <cstdint>

#define NB   32
#define NL   1023
#define NS   1024
#define NH   256
#define NC2  512
#define NE   256
#define NM1  32768
#define NM2  32736

// ---------------- scratch ----------------------------------------------------
__device__ __half g_Gh [NM1 * NE];                 // embeddings fp16
__device__ float  g_Y  [NM2 * NC2];
__device__ __half g_Dh [NM2 * NH];                 // dec_attn fp16
__device__ float  g_SC [(long)NM2 * NS];
__device__ __half g_ATh[(long)NM2 * NS];           // attn probs fp16
__device__ __half g_CWh[NC2 * 1536], g_CWl[NC2 * 1536];  // conv_w 2-limb (FW prep)
__device__ __half g_AWT[NE * 3 * NC2];             // affine_w^T [h|l|h]
__device__ __half g_FWB[NC2 * 768];                // fused weight fp16 [o, tap*256+e]
__device__ __half g_MWb[NC2 * NH];                 // map_w fp16
__device__ __half g_EAb[(long)NB * NS * NH];       // enc_attn fp16
__device__ __half g_SST[(long)NB * NC2 * NS];      // src_seq^T fp16
__device__ float  g_BC [3 * NC2];
__device__ float  g_BR [3 * NC2];

// ---------------- helpers ----------------------------------------------------
__device__ __forceinline__ uint32_t smem_u32(const void* p) {
    uint32_t a;
    asm("{ .reg .u64 t; cvta.to.shared.u64 t, %1; cvt.u32.u64 %0, t; }" : "=r"(a) : "l"(p));
    return a;
}
__device__ __forceinline__ void cpasync16(uint32_t s, const void* g, bool pred) {
    int sz = pred ? 16 : 0;
    asm volatile("cp.async.cg.shared.global [%0], [%1], 16, %2;\n" :: "r"(s), "l"(g), "r"(sz));
}
__device__ __forceinline__ void cp_commit() { asm volatile("cp.async.commit_group;\n" ::: "memory"); }

__device__ __forceinline__ void ldm4(uint32_t* r, uint32_t a) {
    asm volatile("ldmatrix.sync.aligned.m8n8.x4.shared.b16 {%0,%1,%2,%3}, [%4];"
                 : "=r"(r[0]), "=r"(r[1]), "=r"(r[2]), "=r"(r[3]) : "r"(a));
}
__device__ __forceinline__ void mma16816(float* c, const uint32_t* a, const uint32_t* b) {
    asm volatile(
        "mma.sync.aligned.m16n8k16.row.col.f32.f16.f16.f32 "
        "{%0,%1,%2,%3}, {%4,%5,%6,%7}, {%8,%9}, {%0,%1,%2,%3};"
        : "+f"(c[0]), "+f"(c[1]), "+f"(c[2]), "+f"(c[3])
        : "r"(a[0]), "r"(a[1]), "r"(a[2]), "r"(a[3]), "r"(b[0]), "r"(b[1]));
}
__device__ __forceinline__ void split2(float v, __half& h, __half& l) {
    h = __float2half(v);
    l = __float2half(v - __half2float(h));
}

// ---------------- conversion kernels ----------------------------------------
// plain elementwise f32 -> f16, 2 elems/thread
__global__ void cast_h(const float* __restrict__ src, __half* __restrict__ dst, long total2) {
    long gid = (long)blockIdx.x * blockDim.x + threadIdx.x;
    if (gid >= total2) return;
    float2 v = *(const float2*)(src + gid * 2);
    __half2 hh; hh.x = __float2half(v.x); hh.y = __float2half(v.y);
    *(__half2*)(dst + gid * 2) = hh;
}

__global__ void split_flat(const float* __restrict__ src, long total2) {
    long gid = (long)blockIdx.x * blockDim.x + threadIdx.x;
    if (gid >= total2) return;
    float2 v = *(const float2*)(src + gid * 2);
    __half h0, l0, h1, l1;
    split2(v.x, h0, l0); split2(v.y, h1, l1);
    __half2 hh; hh.x = h0; hh.y = h1;
    __half2 ll; ll.x = l0; ll.y = l1;
    *(__half2*)(g_CWh + gid * 2) = hh;
    *(__half2*)(g_CWl + gid * 2) = ll;
}

// affine_w [512(i), 256(e)] -> AWT[e, [hi(512)|lo|hi]]
__global__ void awt_kernel(const float* __restrict__ aw) {
    __shared__ float tile[32][33];
    int i0 = blockIdx.x * 32, e0 = blockIdx.y * 32;
    int tx = threadIdx.x, ty = threadIdx.y;
    tile[ty][tx] = aw[(i0 + ty) * NE + e0 + tx];
    __syncthreads();
    float v = tile[tx][ty];
    __half h, l; split2(v, h, l);
    long base = (long)(e0 + ty) * 1536 + i0 + tx;
    g_AWT[base] = h; g_AWT[base + 512] = l; g_AWT[base + 1024] = h;
}

__global__ void bconst_kernel(const float* __restrict__ cw, const float* __restrict__ ab) {
    int wid = (blockIdx.x * blockDim.x + threadIdx.x) >> 5;
    int lane = threadIdx.x & 31;
    if (wid >= 1536) return;
    int tap = wid / 512, o = wid % 512;
    const float* row = cw + (long)o * 1536 + tap * 512;
    float s = 0.f;
    for (int i = lane; i < 512; i += 32) s += row[i] * ab[i];
    #pragma unroll
    for (int off = 16; off > 0; off >>= 1) s += __shfl_xor_sync(~0u, s, off);
    if (lane == 0) g_BC[tap * 512 + o] = s;
}

__global__ void biasrows_kernel(const float* __restrict__ conv_b) {
    int o = blockIdx.x * blockDim.x + threadIdx.x;
    if (o >= 512) return;
    float b = conv_b[o];
    float c0 = g_BC[o], c1 = g_BC[512 + o], c2 = g_BC[1024 + o];
    g_BR[o]        = b + c2;
    g_BR[512 + o]  = b + c1 + c2;
    g_BR[1024 + o] = b + c0 + c1 + c2;
}

__global__ void gather_h(const int* __restrict__ target, const float* __restrict__ emb) {
    long gid = (long)blockIdx.x * blockDim.x + threadIdx.x;   // over NM1*128
    if (gid >= (long)NM1 * 128) return;
    int m = (int)(gid >> 7);
    int k = ((int)gid & 127) * 2;
    int b = m >> 10, t = m & 1023;
    int idx = target[t * NB + b];
    float2 v = *(const float2*)(emb + (long)idx * NE + k);
    __half2 hh; hh.x = __float2half(v.x); hh.y = __float2half(v.y);
    *(__half2*)(g_Gh + (long)m * NE + k) = hh;
}

// src_seq (b,s,d) f32 -> SST (b, d, s) fp16
__global__ void sst_kernel(const float* __restrict__ src) {
    __shared__ float tile[32][33];
    int b = blockIdx.z;
    int s0 = blockIdx.x * 32, d0 = blockIdx.y * 32;
    int tx = threadIdx.x, ty = threadIdx.y;
    tile[ty][tx] = src[((long)b * NS + s0 + ty) * NC2 + d0 + tx];
    __syncthreads();
    int d = d0 + ty, s = s0 + tx;
    g_SST[((long)b * NC2 + d) * NS + s] = __float2half(tile[tx][ty]);
}

__global__ void glu_kernel() {
    int m = blockIdx.x;
    int h = threadIdx.x;
    float a = g_Y[(long)m * NC2 + h];
    float g = g_Y[(long)m * NC2 + NH + h];
    a = fmaxf(a, 0.f); g = fmaxf(g, 0.f);
    __shared__ float red[8];
    float v = g;
    #pragma unroll
    for (int o = 16; o > 0; o >>= 1) v = fmaxf(v, __shfl_xor_sync(~0u, v, o));
    if ((h & 31) == 0) red[h >> 5] = v;
    __syncthreads();
    float mx = red[0];
    #pragma unroll
    for (int i = 1; i < 8; i++) mx = fmaxf(mx, red[i]);
    float e = expf(g - mx);
    __syncthreads();
    v = e;
    #pragma unroll
    for (int o = 16; o > 0; o >>= 1) v += __shfl_xor_sync(~0u, v, o);
    if ((h & 31) == 0) red[h >> 5] = v;
    __syncthreads();
    float sum = 0.f;
    #pragma unroll
    for (int i = 0; i < 8; i++) sum += red[i];
    g_Dh[(long)m * NH + h] = __float2half(a * e / sum);
}

__global__ void softmax_rows_kernel() {
    int m = blockIdx.x;
    int h = threadIdx.x;
    const float* row = g_SC + (long)m * NS;
    float x0 = row[h], x1 = row[h + 256], x2 = row[h + 512], x3 = row[h + 768];
    __shared__ float red[8];
    float v = fmaxf(fmaxf(x0, x1), fmaxf(x2, x3));
    #pragma unroll
    for (int o = 16; o > 0; o >>= 1) v = fmaxf(v, __shfl_xor_sync(~0u, v, o));
    if ((h & 31) == 0) red[h >> 5] = v;
    __syncthreads();
    float mx = red[0];
    #pragma unroll
    for (int i = 1; i < 8; i++) mx = fmaxf(mx, red[i]);
    float e0 = expf(x0 - mx), e1 = expf(x1 - mx), e2 = expf(x2 - mx), e3 = expf(x3 - mx);
    __syncthreads();
    v = e0 + e1 + e2 + e3;
    #pragma unroll
    for (int o = 16; o > 0; o >>= 1) v += __shfl_xor_sync(~0u, v, o);
    if ((h & 31) == 0) red[h >> 5] = v;
    __syncthreads();
    float sum = 0.f;
    #pragma unroll
    for (int i = 0; i < 8; i++) sum += red[i];
    float inv = 1.f / sum;
    long base = (long)m * NS;
    g_ATh[base + h]       = __float2half(e0 * inv);
    g_ATh[base + h + 256] = __float2half(e1 * inv);
    g_ATh[base + h + 512] = __float2half(e2 * inv);
    g_ATh[base + h + 768] = __float2half(e3 * inv);
}

// ---------------- mma.sync fp16 GEMM (128x128, occ 2) ------------------------
// NSEG=1: C = A[M,K] * B[N,K]^T, both single fp16 limb, fp32 accum.
// NSEG=3: C = [Ahi|Ahi|Alo] * [Bh|Bl|Bh]^T (FW precompute).
// AMODE 0: rows (z*Mb + l) * lda + k.  AMODE 2 (fused conv on G): k -> (tap, e),
//          t = l-2+tap, read (z*1024+t)*256 + e; zero-fill t<0.
// EPI: 0 f32+bias1D, 1 f32, 2 f32 accumulate, 3 fp16 plain write (ld cLd),
//      5 f32 + bias2D rows BR[min(l,2)].
#define GEMM_SMEM (4 * 16384)

template <int AMODE, int EPI, int NSEG>
__global__ __launch_bounds__(256, 2)
void gemm_mma(const __half* __restrict__ Ahi, const __half* __restrict__ Alo,
              int KB, int lda, const __half* __restrict__ Bm, long bBatch,
              const float* __restrict__ bias,
              float* __restrict__ C, int cLd,
              __half* __restrict__ Ohi,
              int Mb) {
    extern __shared__ char smem[];
    const uint32_t sb = smem_u32(smem);
    const int tid = threadIdx.x;
    const int z  = blockIdx.z;
    const int l0 = blockIdx.y * 128;
    const int n0 = blockIdx.x * 128;
    const int Kp = NSEG * KB;
    const int NK = Kp / 32;
    const __half* Bb = Bm + (long)z * bBatch;

    auto load_tile = [&](int kt, int st) {
        const int k0 = kt * 32;
        const int seg = (NSEG == 1) ? 0 : (k0 / KB);
        const int rem0 = k0 - seg * KB;
        const __half* Ab = (NSEG == 3 && seg == 2) ? Alo : Ahi;
        const uint32_t sA = sb + st * 16384;
        const uint32_t sB = sA + 8192;
        #pragma unroll
        for (int i = 0; i < 2; i++) {
            int c = tid + i * 256;          // 0..511
            int m = c >> 2, kc = c & 3;
            int l = l0 + m;
            long g; bool ok;
            if (AMODE == 0) {
                ok = (l < Mb);
                g = ((long)z * Mb + l) * (long)lda + rem0 + kc * 8;
            } else {                         // fused conv on G
                int tap = rem0 >> 8;
                int e = (rem0 & 255) + kc * 8;
                int t = l - 2 + tap;
                ok = (l < Mb) && (t >= 0);
                g = ((long)z * 1024 + t) * 256 + e;
            }
            cpasync16(sA + m * 64 + ((uint32_t)(kc ^ (m & 3)) << 4), Ab + (ok ? g : 0), ok);
        }
        #pragma unroll
        for (int i = 0; i < 2; i++) {
            int c = tid + i * 256;
            int n = c >> 2, kc = c & 3;
            cpasync16(sB + n * 64 + ((uint32_t)(kc ^ (n & 3)) << 4),
                      Bb + (long)(n0 + n) * Kp + k0 + kc * 8, true);
        }
        cp_commit();
    };

    float acc[4][4][4];
    #pragma unroll
    for (int i = 0; i < 4; i++)
        #pragma unroll
        for (int j = 0; j < 4; j++)
            #pragma unroll
            for (int q = 0; q < 4; q++) acc[i][j][q] = 0.f;

    const int w = tid >> 5, lid = tid & 31;
    const int wm = w >> 2, wn = w & 3;
    const int rl = wm * 64 + (lid & 15);
    const int aC = lid >> 4;
    const int nl = wn * 32 + ((lid >> 4) << 3) + (lid & 7);
    const int bC = (lid >> 3) & 1;

    load_tile(0, 0); load_tile(1, 1); load_tile(2, 2);

    for (int kt = 0; kt < NK; kt++) {
        const int st = kt & 3;
        asm volatile("cp.async.wait_group 2;\n" ::: "memory");
        __syncthreads();
        if (kt + 3 < NK) load_tile(kt + 3, (kt + 3) & 3);
        else cp_commit();

        const uint32_t sA = sb + st * 16384;
        const uint32_t sB = sA + 8192;
        #pragma unroll
        for (int ks = 0; ks < 2; ks++) {
            uint32_t a[4][4];
            #pragma unroll
            for (int i = 0; i < 4; i++) {
                int r = rl + i * 16;
                ldm4(a[i], sA + r * 64 + ((uint32_t)((ks * 2 + aC) ^ (r & 3)) << 4));
            }
            uint32_t b[4][2];
            #pragma unroll
            for (int jj = 0; jj < 2; jj++) {
                int n = nl + jj * 16;
                uint32_t t[4];
                ldm4(t, sB + n * 64 + ((uint32_t)((ks * 2 + bC) ^ (n & 3)) << 4));
                b[jj * 2][0] = t[0]; b[jj * 2][1] = t[1];
                b[jj * 2 + 1][0] = t[2]; b[jj * 2 + 1][1] = t[3];
            }
            #pragma unroll
            for (int i = 0; i < 4; i++)
                #pragma unroll
                for (int j = 0; j < 4; j++)
                    mma16816(acc[i][j], a[i], b[j]);
        }
    }

    // ---------------- epilogue ----------------
    const int g  = lid >> 2, t4 = lid & 3;
    #pragma unroll
    for (int i = 0; i < 4; i++) {
        #pragma unroll
        for (int h = 0; h < 2; h++) {
            int row = l0 + wm * 64 + i * 16 + g + h * 8;
            if (row >= Mb) continue;
            long grow = (long)z * Mb + row;
            #pragma unroll
            for (int j = 0; j < 4; j++) {
                int col = n0 + wn * 32 + j * 8 + 2 * t4;
                float v0 = acc[i][j][h * 2 + 0];
                float v1 = acc[i][j][h * 2 + 1];
                if (EPI == 0) { v0 += bias[col]; v1 += bias[col + 1]; }
                if (EPI == 5) {
                    int jb = (row < 2) ? row : 2;
                    v0 += bias[jb * 512 + col]; v1 += bias[jb * 512 + col + 1];
                }
                if (EPI == 3) {
                    __half2 hh; hh.x = __float2half(v0); hh.y = __float2half(v1);
                    *(__half2*)(Ohi + grow * (long)cLd + col) = hh;
                } else {
                    float* cp = C + grow * (long)cLd + col;
                    if (EPI == 2) { v0 += cp[0]; v1 += cp[1]; }
                    float2 r; r.x = v0; r.y = v1;
                    *(float2*)cp = r;
                }
            }
        }
    }
}

// ---------------- launcher ---------------------------------------------------
extern "C" void kernel_launch(void* const* d_in, const int* in_sizes, int n_in,
                              void* d_out, int out_size) {
    const int*   target   = (const int*)d_in[1];
    const float* enc_attn = (const float*)d_in[2];
    const float* src_seq  = (const float*)d_in[3];
    const float* emb      = (const float*)d_in[4];
    const float* affine_w = (const float*)d_in[5];
    const float* affine_b = (const float*)d_in[6];
    const float* conv_w   = (const float*)d_in[7];
    const float* conv_b   = (const float*)d_in[8];
    const float* map_w    = (const float*)d_in[9];
    const float* map_b    = (const float*)d_in[10];
    float* out = (float*)d_out;

    __half *Gh, *Dh, *ATh, *CWh, *CWl, *AWT, *FWB, *MWb, *EAb, *SST;
    float *Y, *SC, *BR;
    cudaGetSymbolAddress((void**)&Gh,  g_Gh);
    cudaGetSymbolAddress((void**)&Y,   g_Y);
    cudaGetSymbolAddress((void**)&Dh,  g_Dh);
    cudaGetSymbolAddress((void**)&SC,  g_SC);
    cudaGetSymbolAddress((void**)&ATh, g_ATh);
    cudaGetSymbolAddress((void**)&CWh, g_CWh);   cudaGetSymbolAddress((void**)&CWl, g_CWl);
    cudaGetSymbolAddress((void**)&AWT, g_AWT);   cudaGetSymbolAddress((void**)&FWB, g_FWB);
    cudaGetSymbolAddress((void**)&MWb, g_MWb);   cudaGetSymbolAddress((void**)&EAb, g_EAb);
    cudaGetSymbolAddress((void**)&SST, g_SST);   cudaGetSymbolAddress((void**)&BR,  g_BR);

    cudaFuncSetAttribute(gemm_mma<0, 3, 3>, cudaFuncAttributeMaxDynamicSharedMemorySize, GEMM_SMEM);
    cudaFuncSetAttribute(gemm_mma<2, 5, 1>, cudaFuncAttributeMaxDynamicSharedMemorySize, GEMM_SMEM);
    cudaFuncSetAttribute(gemm_mma<0, 0, 1>, cudaFuncAttributeMaxDynamicSharedMemorySize, GEMM_SMEM);
    cudaFuncSetAttribute(gemm_mma<0, 1, 1>, cudaFuncAttributeMaxDynamicSharedMemorySize, GEMM_SMEM);
    cudaFuncSetAttribute(gemm_mma<0, 2, 1>, cudaFuncAttributeMaxDynamicSharedMemorySize, GEMM_SMEM);

    // conversions / weight prep
    split_flat<<<(512 * 1536 / 2 + 255) / 256, 256>>>(conv_w, 512 * 1536 / 2);
    awt_kernel<<<dim3(16, 8), dim3(32, 32)>>>(affine_w);
    bconst_kernel<<<192, 256>>>(conv_w, affine_b);
    biasrows_kernel<<<2, 256>>>(conv_b);
    cast_h<<<(512 * 256 / 2 + 255) / 256, 256>>>(map_w, MWb, 512 * 256 / 2);
    cast_h<<<(int)(((long)NM1 * 128 + 255) / 256), 256>>>(enc_attn, EAb, (long)NM1 * 128);
    sst_kernel<<<dim3(NS / 32, NC2 / 32, NB), dim3(32, 32)>>>(src_seq);
    gather_h<<<(int)(((long)NM1 * 128 + 255) / 256), 256>>>(target, emb);

    // 0. fused weight (3-term): FW_tap[o,e] = conv_w[o,tap,:] @ affine_w[:,e]
    for (int tap = 0; tap < 3; tap++)
        gemm_mma<0, 3, 3><<<dim3(2, 4, 1), 256, GEMM_SMEM>>>(
            CWh + tap * 512, CWl + tap * 512, 512, 1536, AWT, 0,
            nullptr, nullptr, 768, FWB + tap * 256, 512);

    // 1. fused conv on G: Y = im2col_E(G) @ FW^T + biasrows  (M=1023/b, N=512, K=768)
    gemm_mma<2, 5, 1><<<dim3(4, 8, NB), 256, GEMM_SMEM>>>(
        Gh, nullptr, 768, 0, FWB, 0, BR, Y, 512, nullptr, NL);
    // 2. GLU
    glu_kernel<<<NM2, 256>>>();
    // 3. map: out = dec @ MW^T + b            (M=1023/b, N=512, K=256)
    gemm_mma<0, 0, 1><<<dim3(4, 8, NB), 256, GEMM_SMEM>>>(
        Dh, nullptr, 256, 256, MWb, 0, map_b, out, 512, nullptr, NL);
    // 4. scores = dec @ enc^T (batched)       (N=1024, K=256)
    gemm_mma<0, 1, 1><<<dim3(8, 8, NB), 256, GEMM_SMEM>>>(
        Dh, nullptr, 256, 256, EAb, (long)NS * NH, nullptr, SC, NS, nullptr, NL);
    // 5. softmax -> fp16 attn probs
    softmax_rows_kernel<<<NM2, 256>>>();
    // 6. out += attn @ src_seq (batched)      (N=512, K=1024)
    gemm_mma<0, 2, 1><<<dim3(4, 8, NB), 256, GEMM_SMEM>>>(
        ATh, nullptr, 1024, 1024, SST, (long)NC2 * NS, nullptr, out, 512, nullptr, NL);
}

// round 9
// speedup vs baseline: 2.4829x; 1.0480x over previous
#include <cuda_runtime.h>
#include <cuda_fp16.h>
#include <cstdint>

#define NB   32
#define NL   1023
#define NS   1024
#define NH   256
#define NC2  512
#define NE   256
#define NM1  32768
#define NM2  32736

// ---------------- scratch ----------------------------------------------------
__device__ __half g_Gh [NM1 * NE];                 // embeddings fp16
__device__ __half g_Yh [NM2 * NC2];                // conv out fp16
__device__ __half g_Dh [NM2 * NH];                 // dec_attn fp16
__device__ __half g_SCh[(long)NM2 * NS];           // scores fp16
__device__ __half g_ATh[(long)NM2 * NS];           // attn probs fp16
__device__ __half g_CWh[NC2 * 1536], g_CWl[NC2 * 1536];  // conv_w 2-limb (FW prep)
__device__ __half g_AWT[NE * 3 * NC2];             // affine_w^T [h|l|h]
__device__ __half g_FWB[NC2 * 768];                // fused weight fp16
__device__ __half g_MWb[NC2 * NH];                 // map_w fp16
__device__ __half g_EAb[(long)NB * NS * NH];       // enc_attn fp16
__device__ __half g_SST[(long)NB * NC2 * NS];      // src_seq^T fp16 (b,d,s)
__device__ float  g_BC [3 * NC2];
__device__ float  g_BR [3 * NC2];

// ---------------- helpers ----------------------------------------------------
__device__ __forceinline__ uint32_t smem_u32(const void* p) {
    uint32_t a;
    asm("{ .reg .u64 t; cvta.to.shared.u64 t, %1; cvt.u32.u64 %0, t; }" : "=r"(a) : "l"(p));
    return a;
}
__device__ __forceinline__ void cpasync16(uint32_t s, const void* g, bool pred) {
    int sz = pred ? 16 : 0;
    asm volatile("cp.async.cg.shared.global [%0], [%1], 16, %2;\n" :: "r"(s), "l"(g), "r"(sz));
}
__device__ __forceinline__ void cp_commit() { asm volatile("cp.async.commit_group;\n" ::: "memory"); }

__device__ __forceinline__ void ldm4(uint32_t* r, uint32_t a) {
    asm volatile("ldmatrix.sync.aligned.m8n8.x4.shared.b16 {%0,%1,%2,%3}, [%4];"
                 : "=r"(r[0]), "=r"(r[1]), "=r"(r[2]), "=r"(r[3]) : "r"(a));
}
__device__ __forceinline__ void mma16816(float* c, const uint32_t* a, const uint32_t* b) {
    asm volatile(
        "mma.sync.aligned.m16n8k16.row.col.f32.f16.f16.f32 "
        "{%0,%1,%2,%3}, {%4,%5,%6,%7}, {%8,%9}, {%0,%1,%2,%3};"
        : "+f"(c[0]), "+f"(c[1]), "+f"(c[2]), "+f"(c[3])
        : "r"(a[0]), "r"(a[1]), "r"(a[2]), "r"(a[3]), "r"(b[0]), "r"(b[1]));
}
__device__ __forceinline__ void split2(float v, __half& h, __half& l) {
    h = __float2half(v);
    l = __float2half(v - __half2float(h));
}

// ---------------- conversion kernels ----------------------------------------
__global__ void cast_h(const float* __restrict__ src, __half* __restrict__ dst, long total2) {
    long gid = (long)blockIdx.x * blockDim.x + threadIdx.x;
    if (gid >= total2) return;
    float2 v = *(const float2*)(src + gid * 2);
    __half2 hh; hh.x = __float2half(v.x); hh.y = __float2half(v.y);
    *(__half2*)(dst + gid * 2) = hh;
}

__global__ void split_flat(const float* __restrict__ src, long total2) {
    long gid = (long)blockIdx.x * blockDim.x + threadIdx.x;
    if (gid >= total2) return;
    float2 v = *(const float2*)(src + gid * 2);
    __half h0, l0, h1, l1;
    split2(v.x, h0, l0); split2(v.y, h1, l1);
    __half2 hh; hh.x = h0; hh.y = h1;
    __half2 ll; ll.x = l0; ll.y = l1;
    *(__half2*)(g_CWh + gid * 2) = hh;
    *(__half2*)(g_CWl + gid * 2) = ll;
}

__global__ void awt_kernel(const float* __restrict__ aw) {
    __shared__ float tile[32][33];
    int i0 = blockIdx.x * 32, e0 = blockIdx.y * 32;
    int tx = threadIdx.x, ty = threadIdx.y;
    tile[ty][tx] = aw[(i0 + ty) * NE + e0 + tx];
    __syncthreads();
    float v = tile[tx][ty];
    __half h, l; split2(v, h, l);
    long base = (long)(e0 + ty) * 1536 + i0 + tx;
    g_AWT[base] = h; g_AWT[base + 512] = l; g_AWT[base + 1024] = h;
}

__global__ void bconst_kernel(const float* __restrict__ cw, const float* __restrict__ ab) {
    int wid = (blockIdx.x * blockDim.x + threadIdx.x) >> 5;
    int lane = threadIdx.x & 31;
    if (wid >= 1536) return;
    int tap = wid / 512, o = wid % 512;
    const float* row = cw + (long)o * 1536 + tap * 512;
    float s = 0.f;
    for (int i = lane; i < 512; i += 32) s += row[i] * ab[i];
    #pragma unroll
    for (int off = 16; off > 0; off >>= 1) s += __shfl_xor_sync(~0u, s, off);
    if (lane == 0) g_BC[tap * 512 + o] = s;
}

__global__ void biasrows_kernel(const float* __restrict__ conv_b) {
    int o = blockIdx.x * blockDim.x + threadIdx.x;
    if (o >= 512) return;
    float b = conv_b[o];
    float c0 = g_BC[o], c1 = g_BC[512 + o], c2 = g_BC[1024 + o];
    g_BR[o]        = b + c2;
    g_BR[512 + o]  = b + c1 + c2;
    g_BR[1024 + o] = b + c0 + c1 + c2;
}

__global__ void gather_h(const int* __restrict__ target, const float* __restrict__ emb) {
    long gid = (long)blockIdx.x * blockDim.x + threadIdx.x;   // over NM1*128
    if (gid >= (long)NM1 * 128) return;
    int m = (int)(gid >> 7);
    int k = ((int)gid & 127) * 2;
    int b = m >> 10, t = m & 1023;
    int idx = target[t * NB + b];
    float2 v = *(const float2*)(emb + (long)idx * NE + k);
    __half2 hh; hh.x = __float2half(v.x); hh.y = __float2half(v.y);
    *(__half2*)(g_Gh + (long)m * NE + k) = hh;
}

// src_seq (b,s,d) f32 -> SST (b, d, s) fp16
__global__ void sst_kernel(const float* __restrict__ src) {
    __shared__ float tile[32][33];
    int b = blockIdx.z;
    int s0 = blockIdx.x * 32, d0 = blockIdx.y * 32;
    int tx = threadIdx.x, ty = threadIdx.y;
    tile[ty][tx] = src[((long)b * NS + s0 + ty) * NC2 + d0 + tx];
    __syncthreads();
    int d = d0 + ty, s = s0 + tx;
    g_SST[((long)b * NC2 + d) * NS + s] = __float2half(tile[tx][ty]);
}

__global__ void glu_kernel() {
    int m = blockIdx.x;
    int h = threadIdx.x;
    float a = __half2float(g_Yh[(long)m * NC2 + h]);
    float g = __half2float(g_Yh[(long)m * NC2 + NH + h]);
    a = fmaxf(a, 0.f); g = fmaxf(g, 0.f);
    __shared__ float red[8];
    float v = g;
    #pragma unroll
    for (int o = 16; o > 0; o >>= 1) v = fmaxf(v, __shfl_xor_sync(~0u, v, o));
    if ((h & 31) == 0) red[h >> 5] = v;
    __syncthreads();
    float mx = red[0];
    #pragma unroll
    for (int i = 1; i < 8; i++) mx = fmaxf(mx, red[i]);
    float e = expf(g - mx);
    __syncthreads();
    v = e;
    #pragma unroll
    for (int o = 16; o > 0; o >>= 1) v += __shfl_xor_sync(~0u, v, o);
    if ((h & 31) == 0) red[h >> 5] = v;
    __syncthreads();
    float sum = 0.f;
    #pragma unroll
    for (int i = 0; i < 8; i++) sum += red[i];
    g_Dh[(long)m * NH + h] = __float2half(a * e / sum);
}

// softmax over fp16 scores -> fp16 probs (half2 path)
__global__ void softmax_rows_kernel() {
    int m = blockIdx.x;
    int h = threadIdx.x;       // 0..255
    const __half2* row = (const __half2*)(g_SCh + (long)m * NS);
    __half2 p0 = row[h];            // elems 2h, 2h+1
    __half2 p1 = row[256 + h];      // elems 512+2h, 512+2h+1
    float x0 = __low2float(p0), x1 = __high2float(p0);
    float x2 = __low2float(p1), x3 = __high2float(p1);
    __shared__ float red[8];
    float v = fmaxf(fmaxf(x0, x1), fmaxf(x2, x3));
    #pragma unroll
    for (int o = 16; o > 0; o >>= 1) v = fmaxf(v, __shfl_xor_sync(~0u, v, o));
    if ((h & 31) == 0) red[h >> 5] = v;
    __syncthreads();
    float mx = red[0];
    #pragma unroll
    for (int i = 1; i < 8; i++) mx = fmaxf(mx, red[i]);
    float e0 = expf(x0 - mx), e1 = expf(x1 - mx), e2 = expf(x2 - mx), e3 = expf(x3 - mx);
    __syncthreads();
    v = e0 + e1 + e2 + e3;
    #pragma unroll
    for (int o = 16; o > 0; o >>= 1) v += __shfl_xor_sync(~0u, v, o);
    if ((h & 31) == 0) red[h >> 5] = v;
    __syncthreads();
    float sum = 0.f;
    #pragma unroll
    for (int i = 0; i < 8; i++) sum += red[i];
    float inv = 1.f / sum;
    __half2* orow = (__half2*)(g_ATh + (long)m * NS);
    __half2 q0; q0.x = __float2half(e0 * inv); q0.y = __float2half(e1 * inv);
    __half2 q1; q1.x = __float2half(e2 * inv); q1.y = __float2half(e3 * inv);
    orow[h] = q0;
    orow[256 + h] = q1;
}

// ---------------- mma.sync fp16 GEMM (128x128, occ 2) ------------------------
// AMODE 0: A rows (z*Mb + l)*lda + k.
// AMODE 2: fused conv on G: k -> (tap, e), t = l-2+tap, zero-fill t<0.
// AMODE 3: concat A: k<256 -> Ahi (Dh, ld 256); k>=256 -> Alo (ATh, ld 1024).
// BCAT: B concat: k<256 -> Bm (MWb, ld 256, unbatched); k>=256 -> B2 (SST, ld 1024, batched).
// NSEG 3 (FW precompute): A = [Ahi|Ahi|Alo], B 3-seg.
// EPI: 0 f32 + bias1D, 3 fp16 plain write (Ohi, ld cLd), 5 fp16 + bias2D BR[min(l,2)].
#define GEMM_SMEM (4 * 16384)

template <int AMODE, int EPI, int NSEG, bool BCAT>
__global__ __launch_bounds__(256, 2)
void gemm_mma(const __half* __restrict__ Ahi, const __half* __restrict__ Alo,
              int KB, int lda, const __half* __restrict__ Bm, long bBatch,
              const __half* __restrict__ B2,
              const float* __restrict__ bias,
              float* __restrict__ C, int cLd,
              __half* __restrict__ Ohi,
              int Mb) {
    extern __shared__ char smem[];
    const uint32_t sb = smem_u32(smem);
    const int tid = threadIdx.x;
    const int z  = blockIdx.z;
    const int l0 = blockIdx.y * 128;
    const int n0 = blockIdx.x * 128;
    const int Kp = NSEG * KB;
    const int NK = Kp / 32;
    const __half* Bb = Bm + (long)z * bBatch;

    auto load_tile = [&](int kt, int st) {
        const int k0 = kt * 32;
        const uint32_t sA = sb + st * 16384;
        const uint32_t sB = sA + 8192;
        // ---- A ----
        {
            const int seg = (NSEG == 3) ? (k0 / KB) : 0;
            const int rem0 = (NSEG == 3) ? (k0 - seg * KB) : k0;
            #pragma unroll
            for (int i = 0; i < 2; i++) {
                int c = tid + i * 256;
                int m = c >> 2, kc = c & 3;
                int l = l0 + m;
                long g; bool ok; const __half* Ab;
                if (AMODE == 0) {
                    ok = (l < Mb);
                    g = ((long)z * Mb + l) * (long)lda + rem0 + kc * 8;
                    Ab = (NSEG == 3 && seg == 2) ? Alo : Ahi;
                } else if (AMODE == 2) {   // fused conv on G
                    int tap = rem0 >> 8;
                    int e = (rem0 & 255) + kc * 8;
                    int t = l - 2 + tap;
                    ok = (l < Mb) && (t >= 0);
                    g = ((long)z * 1024 + t) * 256 + e;
                    Ab = Ahi;
                } else {                   // AMODE 3: concat Dh | ATh
                    ok = (l < Mb);
                    if (k0 < 256) { g = ((long)z * Mb + l) * 256 + k0 + kc * 8; Ab = Ahi; }
                    else          { g = ((long)z * Mb + l) * 1024 + (k0 - 256) + kc * 8; Ab = Alo; }
                }
                cpasync16(sA + m * 64 + ((uint32_t)(kc ^ (m & 3)) << 4), Ab + (ok ? g : 0), ok);
            }
        }
        // ---- B ----
        #pragma unroll
        for (int i = 0; i < 2; i++) {
            int c = tid + i * 256;
            int n = c >> 2, kc = c & 3;
            const __half* src; long g;
            if (BCAT) {
                if (k0 < 256) { src = Bm; g = (long)(n0 + n) * 256 + k0 + kc * 8; }
                else { src = B2; g = ((long)z * 512 + n0 + n) * 1024 + (k0 - 256) + kc * 8; }
            } else {
                src = Bb; g = (long)(n0 + n) * Kp + k0 + kc * 8;
            }
            cpasync16(sB + n * 64 + ((uint32_t)(kc ^ (n & 3)) << 4), src + g, true);
        }
        cp_commit();
    };

    float acc[4][4][4];
    #pragma unroll
    for (int i = 0; i < 4; i++)
        #pragma unroll
        for (int j = 0; j < 4; j++)
            #pragma unroll
            for (int q = 0; q < 4; q++) acc[i][j][q] = 0.f;

    const int w = tid >> 5, lid = tid & 31;
    const int wm = w >> 2, wn = w & 3;
    const int rl = wm * 64 + (lid & 15);
    const int aC = lid >> 4;
    const int nl = wn * 32 + ((lid >> 4) << 3) + (lid & 7);
    const int bC = (lid >> 3) & 1;

    load_tile(0, 0); load_tile(1, 1); load_tile(2, 2);

    for (int kt = 0; kt < NK; kt++) {
        const int st = kt & 3;
        asm volatile("cp.async.wait_group 2;\n" ::: "memory");
        __syncthreads();
        if (kt + 3 < NK) load_tile(kt + 3, (kt + 3) & 3);
        else cp_commit();

        const uint32_t sA = sb + st * 16384;
        const uint32_t sB = sA + 8192;
        #pragma unroll
        for (int ks = 0; ks < 2; ks++) {
            uint32_t a[4][4];
            #pragma unroll
            for (int i = 0; i < 4; i++) {
                int r = rl + i * 16;
                ldm4(a[i], sA + r * 64 + ((uint32_t)((ks * 2 + aC) ^ (r & 3)) << 4));
            }
            uint32_t b[4][2];
            #pragma unroll
            for (int jj = 0; jj < 2; jj++) {
                int n = nl + jj * 16;
                uint32_t t[4];
                ldm4(t, sB + n * 64 + ((uint32_t)((ks * 2 + bC) ^ (n & 3)) << 4));
                b[jj * 2][0] = t[0]; b[jj * 2][1] = t[1];
                b[jj * 2 + 1][0] = t[2]; b[jj * 2 + 1][1] = t[3];
            }
            #pragma unroll
            for (int i = 0; i < 4; i++)
                #pragma unroll
                for (int j = 0; j < 4; j++)
                    mma16816(acc[i][j], a[i], b[j]);
        }
    }

    // ---------------- epilogue ----------------
    const int g  = lid >> 2, t4 = lid & 3;
    #pragma unroll
    for (int i = 0; i < 4; i++) {
        #pragma unroll
        for (int h = 0; h < 2; h++) {
            int row = l0 + wm * 64 + i * 16 + g + h * 8;
            if (row >= Mb) continue;
            long grow = (long)z * Mb + row;
            #pragma unroll
            for (int j = 0; j < 4; j++) {
                int col = n0 + wn * 32 + j * 8 + 2 * t4;
                float v0 = acc[i][j][h * 2 + 0];
                float v1 = acc[i][j][h * 2 + 1];
                if (EPI == 0) { v0 += bias[col]; v1 += bias[col + 1]; }
                if (EPI == 5) {
                    int jb = (row < 2) ? row : 2;
                    v0 += bias[jb * 512 + col]; v1 += bias[jb * 512 + col + 1];
                }
                if (EPI == 3 || EPI == 5) {
                    __half2 hh; hh.x = __float2half(v0); hh.y = __float2half(v1);
                    *(__half2*)(Ohi + grow * (long)cLd + col) = hh;
                } else {
                    float* cp = C + grow * (long)cLd + col;
                    float2 r; r.x = v0; r.y = v1;
                    *(float2*)cp = r;
                }
            }
        }
    }
}

// ---------------- launcher ---------------------------------------------------
extern "C" void kernel_launch(void* const* d_in, const int* in_sizes, int n_in,
                              void* d_out, int out_size) {
    const int*   target   = (const int*)d_in[1];
    const float* enc_attn = (const float*)d_in[2];
    const float* src_seq  = (const float*)d_in[3];
    const float* emb      = (const float*)d_in[4];
    const float* affine_w = (const float*)d_in[5];
    const float* affine_b = (const float*)d_in[6];
    const float* conv_w   = (const float*)d_in[7];
    const float* conv_b   = (const float*)d_in[8];
    const float* map_w    = (const float*)d_in[9];
    const float* map_b    = (const float*)d_in[10];
    float* out = (float*)d_out;

    __half *Gh, *Yh, *Dh, *SCh, *ATh, *CWh, *CWl, *AWT, *FWB, *MWb, *EAb, *SST;
    float *BR;
    cudaGetSymbolAddress((void**)&Gh,  g_Gh);
    cudaGetSymbolAddress((void**)&Yh,  g_Yh);
    cudaGetSymbolAddress((void**)&Dh,  g_Dh);
    cudaGetSymbolAddress((void**)&SCh, g_SCh);
    cudaGetSymbolAddress((void**)&ATh, g_ATh);
    cudaGetSymbolAddress((void**)&CWh, g_CWh);   cudaGetSymbolAddress((void**)&CWl, g_CWl);
    cudaGetSymbolAddress((void**)&AWT, g_AWT);   cudaGetSymbolAddress((void**)&FWB, g_FWB);
    cudaGetSymbolAddress((void**)&MWb, g_MWb);   cudaGetSymbolAddress((void**)&EAb, g_EAb);
    cudaGetSymbolAddress((void**)&SST, g_SST);   cudaGetSymbolAddress((void**)&BR,  g_BR);

    cudaFuncSetAttribute(gemm_mma<0, 3, 3, false>, cudaFuncAttributeMaxDynamicSharedMemorySize, GEMM_SMEM);
    cudaFuncSetAttribute(gemm_mma<2, 5, 1, false>, cudaFuncAttributeMaxDynamicSharedMemorySize, GEMM_SMEM);
    cudaFuncSetAttribute(gemm_mma<0, 3, 1, false>, cudaFuncAttributeMaxDynamicSharedMemorySize, GEMM_SMEM);
    cudaFuncSetAttribute(gemm_mma<3, 0, 1, true>,  cudaFuncAttributeMaxDynamicSharedMemorySize, GEMM_SMEM);

    // conversions / weight prep
    split_flat<<<(512 * 1536 / 2 + 255) / 256, 256>>>(conv_w, 512 * 1536 / 2);
    awt_kernel<<<dim3(16, 8), dim3(32, 32)>>>(affine_w);
    bconst_kernel<<<192, 256>>>(conv_w, affine_b);
    biasrows_kernel<<<2, 256>>>(conv_b);
    cast_h<<<(512 * 256 / 2 + 255) / 256, 256>>>(map_w, MWb, 512 * 256 / 2);
    cast_h<<<(int)(((long)NM1 * 128 + 255) / 256), 256>>>(enc_attn, EAb, (long)NM1 * 128);
    sst_kernel<<<dim3(NS / 32, NC2 / 32, NB), dim3(32, 32)>>>(src_seq);
    gather_h<<<(int)(((long)NM1 * 128 + 255) / 256), 256>>>(target, emb);

    // 0. fused weight (3-term): FW_tap[o,e] = conv_w[o,tap,:] @ affine_w[:,e]
    for (int tap = 0; tap < 3; tap++)
        gemm_mma<0, 3, 3, false><<<dim3(2, 4, 1), 256, GEMM_SMEM>>>(
            CWh + tap * 512, CWl + tap * 512, 512, 1536, AWT, 0, nullptr,
            nullptr, nullptr, 768, FWB + tap * 256, 512);

    // 1. fused conv on G -> Yh fp16 (+bias rows)   (M=1023/b, N=512, K=768)
    gemm_mma<2, 5, 1, false><<<dim3(4, 8, NB), 256, GEMM_SMEM>>>(
        Gh, nullptr, 768, 0, FWB, 0, nullptr, BR, nullptr, 512, Yh, NL);
    // 2. GLU -> Dh
    glu_kernel<<<NM2, 256>>>();
    // 3. scores -> SCh fp16 (batched)              (N=1024, K=256)
    gemm_mma<0, 3, 1, false><<<dim3(8, 8, NB), 256, GEMM_SMEM>>>(
        Dh, nullptr, 256, 256, EAb, (long)NS * NH, nullptr, nullptr, nullptr, NS, SCh, NL);
    // 4. softmax -> ATh fp16
    softmax_rows_kernel<<<NM2, 256>>>();
    // 5. combined: out = [Dh|ATh] @ [map_w|SST]^T + map_b   (N=512, K=1280)
    gemm_mma<3, 0, 1, true><<<dim3(4, 8, NB), 256, GEMM_SMEM>>>(
        Dh, ATh, 1280, 0, MWb, 0, SST, map_b, out, 512, nullptr, NL);
}

// round 10
// speedup vs baseline: 3.1452x; 1.2667x over previous
#include <cuda_runtime.h>
#include <cuda_fp16.h>
#include <cstdint>

#define NB   32
#define NL   1023
#define NS   1024
#define NH   256
#define NC2  512
#define NE   256
#define NM1  32768
#define NM2  32736

// ---------------- scratch ----------------------------------------------------
__device__ __half g_Gh [NM1 * NE];                 // embeddings fp16
__device__ __half g_Yh [NM2 * NC2];                // conv out fp16
__device__ __half g_Dh [NM2 * NH];                 // dec_attn fp16
__device__ __half g_SCh[(long)NM2 * NS];           // scores fp16
__device__ __half g_ATh[(long)NM2 * NS];           // attn probs fp16
__device__ __half g_CWh[NC2 * 1536], g_CWl[NC2 * 1536];  // conv_w 2-limb (FW prep)
__device__ __half g_AWT[NE * 3 * NC2];             // affine_w^T [h|l|h]
__device__ __half g_FWB[NC2 * 768];                // fused weight fp16
__device__ __half g_MWb[NC2 * NH];                 // map_w fp16
__device__ __half g_EAb[(long)NB * NS * NH];       // enc_attn fp16
__device__ __half g_SST[(long)NB * NC2 * NS];      // src_seq^T fp16 (b,d,s)
__device__ float  g_BC [3 * NC2];
__device__ float  g_BR [3 * NC2];

// ---------------- helpers ----------------------------------------------------
__device__ __forceinline__ uint32_t smem_u32(const void* p) {
    uint32_t a;
    asm("{ .reg .u64 t; cvta.to.shared.u64 t, %1; cvt.u32.u64 %0, t; }" : "=r"(a) : "l"(p));
    return a;
}
__device__ __forceinline__ void cpasync16(uint32_t s, const void* g, bool pred) {
    int sz = pred ? 16 : 0;
    asm volatile("cp.async.cg.shared.global [%0], [%1], 16, %2;\n" :: "r"(s), "l"(g), "r"(sz));
}
__device__ __forceinline__ void cp_commit() { asm volatile("cp.async.commit_group;\n" ::: "memory"); }

__device__ __forceinline__ void ldm4(uint32_t* r, uint32_t a) {
    asm volatile("ldmatrix.sync.aligned.m8n8.x4.shared.b16 {%0,%1,%2,%3}, [%4];"
                 : "=r"(r[0]), "=r"(r[1]), "=r"(r[2]), "=r"(r[3]) : "r"(a));
}
__device__ __forceinline__ void mma16816(float* c, const uint32_t* a, const uint32_t* b) {
    asm volatile(
        "mma.sync.aligned.m16n8k16.row.col.f32.f16.f16.f32 "
        "{%0,%1,%2,%3}, {%4,%5,%6,%7}, {%8,%9}, {%0,%1,%2,%3};"
        : "+f"(c[0]), "+f"(c[1]), "+f"(c[2]), "+f"(c[3])
        : "r"(a[0]), "r"(a[1]), "r"(a[2]), "r"(a[3]), "r"(b[0]), "r"(b[1]));
}
__device__ __forceinline__ void split2(float v, __half& h, __half& l) {
    h = __float2half(v);
    l = __float2half(v - __half2float(h));
}

// ---------------- mega prep kernel -------------------------------------------
// block ranges: [0,16384) gather | [16384,32768) enc cast | [32768,33024) map cast
// [33024,34560) split_flat conv_w | [34560,34688) awt | [34688,51072) sst
// [51072,51264) bconst
#define PB_GATHER 0
#define PB_ENC    16384
#define PB_MAP    32768
#define PB_SPLIT  33024
#define PB_AWT    34560
#define PB_SST    34688
#define PB_BCONST 51072
#define PB_TOTAL  51264

__global__ void mega_prep(const int* __restrict__ target,
                          const float* __restrict__ emb,
                          const float* __restrict__ enc_attn,
                          const float* __restrict__ map_w,
                          const float* __restrict__ conv_w,
                          const float* __restrict__ affine_w,
                          const float* __restrict__ affine_b,
                          const float* __restrict__ src_seq) {
    const int bid = blockIdx.x;
    const int tid = threadIdx.x;

    if (bid < PB_ENC) {
        // gather + cast: 2 elems/thread over NM1*256
        long gid = (long)(bid - PB_GATHER) * 256 + tid;
        int m = (int)(gid >> 7);
        int k = ((int)gid & 127) * 2;
        int b = m >> 10, t = m & 1023;
        int idx = target[t * NB + b];
        float2 v = *(const float2*)(emb + (long)idx * NE + k);
        __half2 hh; hh.x = __float2half(v.x); hh.y = __float2half(v.y);
        *(__half2*)(g_Gh + (long)m * NE + k) = hh;
    } else if (bid < PB_MAP) {
        long gid = (long)(bid - PB_ENC) * 256 + tid;
        float2 v = *(const float2*)(enc_attn + gid * 2);
        __half2 hh; hh.x = __float2half(v.x); hh.y = __float2half(v.y);
        *(__half2*)(g_EAb + gid * 2) = hh;
    } else if (bid < PB_SPLIT) {
        long gid = (long)(bid - PB_MAP) * 256 + tid;
        float2 v = *(const float2*)(map_w + gid * 2);
        __half2 hh; hh.x = __float2half(v.x); hh.y = __float2half(v.y);
        *(__half2*)(g_MWb + gid * 2) = hh;
    } else if (bid < PB_AWT) {
        long gid = (long)(bid - PB_SPLIT) * 256 + tid;
        float2 v = *(const float2*)(conv_w + gid * 2);
        __half h0, l0, h1, l1;
        split2(v.x, h0, l0); split2(v.y, h1, l1);
        __half2 hh; hh.x = h0; hh.y = h1;
        __half2 ll; ll.x = l0; ll.y = l1;
        *(__half2*)(g_CWh + gid * 2) = hh;
        *(__half2*)(g_CWl + gid * 2) = ll;
    } else if (bid < PB_SST) {
        // affine_w [512(i),256(e)] -> AWT[e, [hi|lo|hi]] ; 32x32 tile per block
        __shared__ float tile[32][33];
        int lb = bid - PB_AWT;              // 0..127 : 16 i-tiles x 8 e-tiles
        int i0 = (lb >> 3) * 32, e0 = (lb & 7) * 32;
        int tx = tid & 31, ty0 = tid >> 5;  // 8 rows/pass
        #pragma unroll
        for (int p = 0; p < 4; p++) {
            int ty = ty0 + p * 8;
            tile[ty][tx] = affine_w[(i0 + ty) * NE + e0 + tx];
        }
        __syncthreads();
        #pragma unroll
        for (int p = 0; p < 4; p++) {
            int ty = ty0 + p * 8;
            float v = tile[tx][ty];
            __half h, l; split2(v, h, l);
            long base = (long)(e0 + ty) * 1536 + i0 + tx;
            g_AWT[base] = h; g_AWT[base + 512] = l; g_AWT[base + 1024] = h;
        }
    } else if (bid < PB_BCONST) {
        // src_seq (b,s,d) f32 -> SST (b,d,s) fp16 ; 32x32 tile per block
        __shared__ float tile[32][33];
        int lb = bid - PB_SST;              // 0..16383 : b(32) x dy(16) x sx(32)
        int b = lb >> 9;
        int rem = lb & 511;
        int dy = rem >> 5, sx = rem & 31;
        int s0 = sx * 32, d0 = dy * 32;
        int tx = tid & 31, ty0 = tid >> 5;
        #pragma unroll
        for (int p = 0; p < 4; p++) {
            int ty = ty0 + p * 8;
            tile[ty][tx] = src_seq[((long)b * NS + s0 + ty) * NC2 + d0 + tx];
        }
        __syncthreads();
        #pragma unroll
        for (int p = 0; p < 4; p++) {
            int ty = ty0 + p * 8;
            g_SST[((long)b * NC2 + d0 + ty) * NS + s0 + tx] = __float2half(tile[tx][ty]);
        }
    } else {
        // bconst: warp per (tap,o)
        int wid = (bid - PB_BCONST) * 8 + (tid >> 5);
        int lane = tid & 31;
        int tap = wid / 512, o = wid % 512;
        const float* row = conv_w + (long)o * 1536 + tap * 512;
        float s = 0.f;
        for (int i = lane; i < 512; i += 32) s += row[i] * affine_b[i];
        #pragma unroll
        for (int off = 16; off > 0; off >>= 1) s += __shfl_xor_sync(~0u, s, off);
        if (lane == 0) g_BC[tap * 512 + o] = s;
    }
}

__global__ void biasrows_kernel(const float* __restrict__ conv_b) {
    int o = blockIdx.x * blockDim.x + threadIdx.x;
    if (o >= 512) return;
    float b = conv_b[o];
    float c0 = g_BC[o], c1 = g_BC[512 + o], c2 = g_BC[1024 + o];
    g_BR[o]        = b + c2;
    g_BR[512 + o]  = b + c1 + c2;
    g_BR[1024 + o] = b + c0 + c1 + c2;
}

// GLU: 2 rows per block, half2 loads
__global__ void glu_kernel() {
    int r  = threadIdx.x >> 7;                 // row within block
    int m  = blockIdx.x * 2 + r;
    int h2 = threadIdx.x & 127;                // half2 index
    const __half2* yrow = (const __half2*)(g_Yh + (long)m * NC2);
    __half2 a2 = yrow[h2];
    __half2 g2 = yrow[128 + h2];
    float a0 = fmaxf(__low2float(a2), 0.f), a1 = fmaxf(__high2float(a2), 0.f);
    float g0 = fmaxf(__low2float(g2), 0.f), g1 = fmaxf(__high2float(g2), 0.f);
    __shared__ float red[2][4];
    int lane = threadIdx.x & 31, wIn = (threadIdx.x >> 5) & 3;
    float v = fmaxf(g0, g1);
    #pragma unroll
    for (int o = 16; o > 0; o >>= 1) v = fmaxf(v, __shfl_xor_sync(~0u, v, o));
    if (lane == 0) red[r][wIn] = v;
    __syncthreads();
    float mx = fmaxf(fmaxf(red[r][0], red[r][1]), fmaxf(red[r][2], red[r][3]));
    float e0 = expf(g0 - mx), e1 = expf(g1 - mx);
    __syncthreads();
    v = e0 + e1;
    #pragma unroll
    for (int o = 16; o > 0; o >>= 1) v += __shfl_xor_sync(~0u, v, o);
    if (lane == 0) red[r][wIn] = v;
    __syncthreads();
    float sum = red[r][0] + red[r][1] + red[r][2] + red[r][3];
    float inv = 1.f / sum;
    __half2 d2; d2.x = __float2half(a0 * e0 * inv); d2.y = __float2half(a1 * e1 * inv);
    *(__half2*)(g_Dh + (long)m * NH + 2 * h2) = d2;
}

// softmax over fp16 scores -> fp16 probs
__global__ void softmax_rows_kernel() {
    int m = blockIdx.x;
    int h = threadIdx.x;
    const __half2* row = (const __half2*)(g_SCh + (long)m * NS);
    __half2 p0 = row[h];
    __half2 p1 = row[256 + h];
    float x0 = __low2float(p0), x1 = __high2float(p0);
    float x2 = __low2float(p1), x3 = __high2float(p1);
    __shared__ float red[8];
    float v = fmaxf(fmaxf(x0, x1), fmaxf(x2, x3));
    #pragma unroll
    for (int o = 16; o > 0; o >>= 1) v = fmaxf(v, __shfl_xor_sync(~0u, v, o));
    if ((h & 31) == 0) red[h >> 5] = v;
    __syncthreads();
    float mx = red[0];
    #pragma unroll
    for (int i = 1; i < 8; i++) mx = fmaxf(mx, red[i]);
    float e0 = expf(x0 - mx), e1 = expf(x1 - mx), e2 = expf(x2 - mx), e3 = expf(x3 - mx);
    __syncthreads();
    v = e0 + e1 + e2 + e3;
    #pragma unroll
    for (int o = 16; o > 0; o >>= 1) v += __shfl_xor_sync(~0u, v, o);
    if ((h & 31) == 0) red[h >> 5] = v;
    __syncthreads();
    float sum = 0.f;
    #pragma unroll
    for (int i = 0; i < 8; i++) sum += red[i];
    float inv = 1.f / sum;
    __half2* orow = (__half2*)(g_ATh + (long)m * NS);
    __half2 q0; q0.x = __float2half(e0 * inv); q0.y = __float2half(e1 * inv);
    __half2 q1; q1.x = __float2half(e2 * inv); q1.y = __float2half(e3 * inv);
    orow[h] = q0;
    orow[256 + h] = q1;
}

// ---------------- mma.sync fp16 GEMM (128x128, occ 2) ------------------------
// AMODE 0: A rows; if aBatch!=0, A ptr pre-offset by z*aBatch and rows indexed by l only.
// AMODE 2: fused conv on G. AMODE 3: concat Dh|ATh. BCAT: B concat map_w|SST.
// NSEG 3: A=[Ahi|Ahi|Alo], B 3-seg (FW precompute).
// EPI: 0 f32+bias1D, 3 fp16 write, 5 fp16+bias2D BR[min(l,2)].
#define GEMM_SMEM (4 * 16384)

template <int AMODE, int EPI, int NSEG, bool BCAT>
__global__ __launch_bounds__(256, 2)
void gemm_mma(const __half* __restrict__ Ahi, const __half* __restrict__ Alo, long aBatch,
              int KB, int lda, const __half* __restrict__ Bm, long bBatch,
              const __half* __restrict__ B2,
              const float* __restrict__ bias,
              float* __restrict__ C, int cLd,
              __half* __restrict__ Ohi, long oBatch,
              int Mb) {
    extern __shared__ char smem[];
    const uint32_t sb = smem_u32(smem);
    const int tid = threadIdx.x;
    const int z  = blockIdx.z;
    const int l0 = blockIdx.y * 128;
    const int n0 = blockIdx.x * 128;
    const int Kp = NSEG * KB;
    const int NK = Kp / 32;
    const __half* Bb = Bm + (long)z * bBatch;
    Ahi += (long)z * aBatch;
    if (NSEG == 3) Alo += (long)z * aBatch;

    auto load_tile = [&](int kt, int st) {
        const int k0 = kt * 32;
        const uint32_t sA = sb + st * 16384;
        const uint32_t sB = sA + 8192;
        {
            const int seg = (NSEG == 3) ? (k0 / KB) : 0;
            const int rem0 = (NSEG == 3) ? (k0 - seg * KB) : k0;
            #pragma unroll
            for (int i = 0; i < 2; i++) {
                int c = tid + i * 256;
                int m = c >> 2, kc = c & 3;
                int l = l0 + m;
                long g; bool ok; const __half* Ab;
                if (AMODE == 0) {
                    ok = (l < Mb);
                    long rowbase = aBatch ? (long)l : ((long)z * Mb + l);
                    g = rowbase * (long)lda + rem0 + kc * 8;
                    Ab = (NSEG == 3 && seg == 2) ? Alo : Ahi;
                } else if (AMODE == 2) {   // fused conv on G
                    int tap = rem0 >> 8;
                    int e = (rem0 & 255) + kc * 8;
                    int t = l - 2 + tap;
                    ok = (l < Mb) && (t >= 0);
                    g = ((long)z * 1024 + t) * 256 + e;
                    Ab = Ahi;
                } else {                   // AMODE 3: concat Dh | ATh
                    ok = (l < Mb);
                    if (k0 < 256) { g = ((long)z * Mb + l) * 256 + k0 + kc * 8; Ab = Ahi; }
                    else          { g = ((long)z * Mb + l) * 1024 + (k0 - 256) + kc * 8; Ab = Alo; }
                }
                cpasync16(sA + m * 64 + ((uint32_t)(kc ^ (m & 3)) << 4), Ab + (ok ? g : 0), ok);
            }
        }
        #pragma unroll
        for (int i = 0; i < 2; i++) {
            int c = tid + i * 256;
            int n = c >> 2, kc = c & 3;
            const __half* src; long g;
            if (BCAT) {
                if (k0 < 256) { src = Bm; g = (long)(n0 + n) * 256 + k0 + kc * 8; }
                else { src = B2; g = ((long)z * 512 + n0 + n) * 1024 + (k0 - 256) + kc * 8; }
            } else {
                src = Bb; g = (long)(n0 + n) * Kp + k0 + kc * 8;
            }
            cpasync16(sB + n * 64 + ((uint32_t)(kc ^ (n & 3)) << 4), src + g, true);
        }
        cp_commit();
    };

    float acc[4][4][4];
    #pragma unroll
    for (int i = 0; i < 4; i++)
        #pragma unroll
        for (int j = 0; j < 4; j++)
            #pragma unroll
            for (int q = 0; q < 4; q++) acc[i][j][q] = 0.f;

    const int w = tid >> 5, lid = tid & 31;
    const int wm = w >> 2, wn = w & 3;
    const int rl = wm * 64 + (lid & 15);
    const int aC = lid >> 4;
    const int nl = wn * 32 + ((lid >> 4) << 3) + (lid & 7);
    const int bC = (lid >> 3) & 1;

    load_tile(0, 0); load_tile(1, 1); load_tile(2, 2);

    for (int kt = 0; kt < NK; kt++) {
        const int st = kt & 3;
        asm volatile("cp.async.wait_group 2;\n" ::: "memory");
        __syncthreads();
        if (kt + 3 < NK) load_tile(kt + 3, (kt + 3) & 3);
        else cp_commit();

        const uint32_t sA = sb + st * 16384;
        const uint32_t sB = sA + 8192;
        #pragma unroll
        for (int ks = 0; ks < 2; ks++) {
            uint32_t a[4][4];
            #pragma unroll
            for (int i = 0; i < 4; i++) {
                int r = rl + i * 16;
                ldm4(a[i], sA + r * 64 + ((uint32_t)((ks * 2 + aC) ^ (r & 3)) << 4));
            }
            uint32_t b[4][2];
            #pragma unroll
            for (int jj = 0; jj < 2; jj++) {
                int n = nl + jj * 16;
                uint32_t t[4];
                ldm4(t, sB + n * 64 + ((uint32_t)((ks * 2 + bC) ^ (n & 3)) << 4));
                b[jj * 2][0] = t[0]; b[jj * 2][1] = t[1];
                b[jj * 2 + 1][0] = t[2]; b[jj * 2 + 1][1] = t[3];
            }
            #pragma unroll
            for (int i = 0; i < 4; i++)
                #pragma unroll
                for (int j = 0; j < 4; j++)
                    mma16816(acc[i][j], a[i], b[j]);
        }
    }

    // ---------------- epilogue ----------------
    const int g  = lid >> 2, t4 = lid & 3;
    __half* Op = Ohi + (long)z * oBatch;
    #pragma unroll
    for (int i = 0; i < 4; i++) {
        #pragma unroll
        for (int h = 0; h < 2; h++) {
            int row = l0 + wm * 64 + i * 16 + g + h * 8;
            if (row >= Mb) continue;
            long grow = (long)z * Mb + row;
            long orow = oBatch ? (long)row : grow;
            #pragma unroll
            for (int j = 0; j < 4; j++) {
                int col = n0 + wn * 32 + j * 8 + 2 * t4;
                float v0 = acc[i][j][h * 2 + 0];
                float v1 = acc[i][j][h * 2 + 1];
                if (EPI == 0) { v0 += bias[col]; v1 += bias[col + 1]; }
                if (EPI == 5) {
                    int jb = (row < 2) ? row : 2;
                    v0 += bias[jb * 512 + col]; v1 += bias[jb * 512 + col + 1];
                }
                if (EPI == 3 || EPI == 5) {
                    __half2 hh; hh.x = __float2half(v0); hh.y = __float2half(v1);
                    *(__half2*)(Op + orow * (long)cLd + col) = hh;
                } else {
                    float* cp = C + grow * (long)cLd + col;
                    float2 r; r.x = v0; r.y = v1;
                    *(float2*)cp = r;
                }
            }
        }
    }
}

// ---------------- launcher ---------------------------------------------------
extern "C" void kernel_launch(void* const* d_in, const int* in_sizes, int n_in,
                              void* d_out, int out_size) {
    const int*   target   = (const int*)d_in[1];
    const float* enc_attn = (const float*)d_in[2];
    const float* src_seq  = (const float*)d_in[3];
    const float* emb      = (const float*)d_in[4];
    const float* affine_w = (const float*)d_in[5];
    const float* affine_b = (const float*)d_in[6];
    const float* conv_w   = (const float*)d_in[7];
    const float* conv_b   = (const float*)d_in[8];
    const float* map_w    = (const float*)d_in[9];
    const float* map_b    = (const float*)d_in[10];
    float* out = (float*)d_out;

    __half *Gh, *Yh, *Dh, *SCh, *ATh, *CWh, *CWl, *AWT, *FWB, *MWb, *EAb, *SST;
    float *BR;
    cudaGetSymbolAddress((void**)&Gh,  g_Gh);
    cudaGetSymbolAddress((void**)&Yh,  g_Yh);
    cudaGetSymbolAddress((void**)&Dh,  g_Dh);
    cudaGetSymbolAddress((void**)&SCh, g_SCh);
    cudaGetSymbolAddress((void**)&ATh, g_ATh);
    cudaGetSymbolAddress((void**)&CWh, g_CWh);   cudaGetSymbolAddress((void**)&CWl, g_CWl);
    cudaGetSymbolAddress((void**)&AWT, g_AWT);   cudaGetSymbolAddress((void**)&FWB, g_FWB);
    cudaGetSymbolAddress((void**)&MWb, g_MWb);   cudaGetSymbolAddress((void**)&EAb, g_EAb);
    cudaGetSymbolAddress((void**)&SST, g_SST);   cudaGetSymbolAddress((void**)&BR,  g_BR);

    cudaFuncSetAttribute(gemm_mma<0, 3, 3, false>, cudaFuncAttributeMaxDynamicSharedMemorySize, GEMM_SMEM);
    cudaFuncSetAttribute(gemm_mma<2, 5, 1, false>, cudaFuncAttributeMaxDynamicSharedMemorySize, GEMM_SMEM);
    cudaFuncSetAttribute(gemm_mma<0, 3, 1, false>, cudaFuncAttributeMaxDynamicSharedMemorySize, GEMM_SMEM);
    cudaFuncSetAttribute(gemm_mma<3, 0, 1, true>,  cudaFuncAttributeMaxDynamicSharedMemorySize, GEMM_SMEM);

    // 1. all conversions / weight prep in one launch
    mega_prep<<<PB_TOTAL, 256>>>(target, emb, enc_attn, map_w, conv_w,
                                 affine_w, affine_b, src_seq);
    // 2. bias rows
    biasrows_kernel<<<2, 256>>>(conv_b);
    // 3. fused weight (3-term, batched over taps): FW_tap = conv_w[.,tap,:] @ AWT
    gemm_mma<0, 3, 3, false><<<dim3(2, 4, 3), 256, GEMM_SMEM>>>(
        CWh, CWl, 512, 512, 1536, AWT, 0, nullptr,
        nullptr, nullptr, 768, FWB, 256, 512);
    // 4. fused conv on G -> Yh fp16 (+bias rows)   (M=1023/b, N=512, K=768)
    gemm_mma<2, 5, 1, false><<<dim3(4, 8, NB), 256, GEMM_SMEM>>>(
        Gh, nullptr, 0, 768, 0, FWB, 0, nullptr, BR, nullptr, 512, Yh, 0, NL);
    // 5. GLU -> Dh
    glu_kernel<<<NM2 / 2, 256>>>();
    // 6. scores -> SCh fp16 (batched)              (N=1024, K=256)
    gemm_mma<0, 3, 1, false><<<dim3(8, 8, NB), 256, GEMM_SMEM>>>(
        Dh, nullptr, 0, 256, 256, EAb, (long)NS * NH, nullptr,
        nullptr, nullptr, NS, SCh, 0, NL);
    // 7. softmax -> ATh fp16
    softmax_rows_kernel<<<NM2, 256>>>();
    // 8. combined: out = [Dh|ATh] @ [map_w|SST]^T + map_b   (N=512, K=1280)
    gemm_mma<3, 0, 1, true><<<dim3(4, 8, NB), 256, GEMM_SMEM>>>(
        Dh, ATh, 0, 1280, 0, MWb, 0, SST, map_b, out, 512, nullptr, 0, NL);
}